// round 13
// baseline (speedup 1.0000x reference)
#include <cuda_runtime.h>
#include <cuda_fp16.h>
#include <cstdint>
#include <math.h>

#define B 2
#define L 2048
#define HID 2048
#define NH 16
#define NKV 4
#define HDIM 128
#define LAT 512
#define SCALE 0.08838834764831845f /* 1/sqrt(128) */
#define SCALE_L2E 0.1275216702398461f /* SCALE * log2(e) */

// ======================= helpers =======================
__device__ __forceinline__ uint32_t smem_to_u32(const void* p) {
  uint32_t a;
  asm("{ .reg .u64 t; cvta.to.shared.u64 t, %1; cvt.u32.u64 %0, t; }"
      : "=r"(a) : "l"(p));
  return a;
}
__device__ __forceinline__ void cp16(uint32_t dst, const void* src) {
  asm volatile("cp.async.cg.shared.global [%0], [%1], 16;" ::"r"(dst), "l"(src));
}
#define CP_COMMIT() asm volatile("cp.async.commit_group;" ::: "memory")
#define CP_WAIT1() asm volatile("cp.async.wait_group 1;" ::: "memory")
#define CP_WAIT0() asm volatile("cp.async.wait_group 0;" ::: "memory")

__device__ __forceinline__ void ldsm4(uint32_t addr, uint32_t* r) {
  asm volatile("ldmatrix.sync.aligned.m8n8.x4.shared.b16 {%0,%1,%2,%3}, [%4];"
               : "=r"(r[0]), "=r"(r[1]), "=r"(r[2]), "=r"(r[3]) : "r"(addr));
}
__device__ __forceinline__ void ldsm4t(uint32_t addr, uint32_t* r) {
  asm volatile(
      "ldmatrix.sync.aligned.m8n8.x4.trans.shared.b16 {%0,%1,%2,%3}, [%4];"
      : "=r"(r[0]), "=r"(r[1]), "=r"(r[2]), "=r"(r[3]) : "r"(addr));
}
__device__ __forceinline__ void mma16816h(float* c, const uint32_t* a,
                                          const uint32_t* b) {
  asm volatile(
      "mma.sync.aligned.m16n8k16.row.col.f32.f16.f16.f32 "
      "{%0,%1,%2,%3}, {%4,%5,%6,%7}, {%8,%9}, {%0,%1,%2,%3};"
      : "+f"(c[0]), "+f"(c[1]), "+f"(c[2]), "+f"(c[3])
      : "r"(a[0]), "r"(a[1]), "r"(a[2]), "r"(a[3]), "r"(b[0]), "r"(b[1]));
}
__device__ __forceinline__ uint32_t pk2h(float lo, float hi) {
  __half2 h = __floats2half2_rn(lo, hi);
  return *(uint32_t*)&h;
}
__device__ __forceinline__ float ex2(float x) {
  float y;
  asm("ex2.approx.f32 %0, %1;" : "=f"(y) : "f"(x));
  return y;
}

// ======================= scratch =======================
__device__ float2 g_tab[(size_t)L * 64];  // RoPE cos/sin table

__device__ __half g_xf[(size_t)B * L * HID];
__device__ __half g_cf[(size_t)B * L * LAT];
__device__ __half g_Qf[(size_t)B * L * NH * HDIM];
__device__ __half g_Kf[(size_t)B * L * NKV * HDIM];
__device__ __half g_Vf[(size_t)B * L * NKV * HDIM];
__device__ __half g_Yf[(size_t)B * L * HID];
__device__ __half g_Wqt_f[(size_t)NH * HDIM * HID];
__device__ __half g_Wct_f[(size_t)LAT * HID];
__device__ __half g_Wkvt_f[(size_t)2 * NKV * HDIM * LAT];  // [Wk; Wv] rows
__device__ __half g_Wot_f[(size_t)HID * NH * HDIM];

// ======================= stream context (created pre-main) ==============
namespace {
struct Ctx {
  cudaStream_t side;
  cudaEvent_t e0, e1;
  Ctx() {
    cudaStreamCreateWithFlags(&side, cudaStreamNonBlocking);
    cudaEventCreateWithFlags(&e0, cudaEventDisableTiming);
    cudaEventCreateWithFlags(&e1, cudaEventDisableTiming);
  }
};
Ctx g_ctx;
}  // namespace

// ======================= preprocessing =======================
__global__ void split_f16_kernel(const float* __restrict__ s,
                                 __half* __restrict__ f, int n4) {
  int i = blockIdx.x * blockDim.x + threadIdx.x;
  if (i >= n4) return;
  float4 v = ((const float4*)s)[i];
  ((__half2*)f)[2 * i] = __floats2half2_rn(v.x, v.y);
  ((__half2*)f)[2 * i + 1] = __floats2half2_rn(v.z, v.w);
}

// W[K,N] fp32 -> Wt[N,K] fp16
__global__ __launch_bounds__(256) void tsplit_f16_kernel(
    const float* __restrict__ W, __half* __restrict__ f, int K, int N) {
  __shared__ float t[32][33];
  const int n0 = blockIdx.x * 32, k0 = blockIdx.y * 32;
  const int tx = threadIdx.x & 31, ty = threadIdx.x >> 5;
#pragma unroll
  for (int i = 0; i < 32; i += 8)
    t[ty + i][tx] = W[(size_t)(k0 + ty + i) * N + n0 + tx];
  __syncthreads();
#pragma unroll
  for (int i = 0; i < 32; i += 8)
    f[(size_t)(n0 + ty + i) * K + k0 + tx] = __float2half(t[tx][ty + i]);
}

// RoPE table: tab[l][hf] = (cos, sin)(l * 10000^(-hf/64)), double precision
__global__ void rope_tab_kernel(float2* __restrict__ tab) {
  int i = blockIdx.x * blockDim.x + threadIdx.x;
  if (i >= L * 64) return;
  const int hf = i & 63;
  const int l = i >> 6;
  const double inv = exp(-(double)hf * 0.14391156831212788);
  const double fr = (double)l * inv;
  tab[i] = make_float2((float)cos(fr), (float)sin(fr));
}

// ======================= fp16 GEMM: 64x64 warp tiles =======================
// C[M,N] = A[M,K] @ B[N,K]^T, fp16 in, fp32 accum. 4 warps/CTA, 3-stage.
// mode 0: fp32 out to C
// mode 1: fp16 out to C16
// mode 3: RoPE epilogue -> Crope ([B*L, NHD, 128] fp16), scale scl
// mode 4: KV: cols<512 RoPE -> Crope (NKV heads), cols>=512 fp16 -> C16
#define BM 128
#define BN 128
#define FBK 64
#define FTILEB 16384u
#define FSTAGEB 32768u
#define GSMEM_F16 (3 * 32768)

__global__ __launch_bounds__(128, 2) void mma_gemm_f16(
    const __half* __restrict__ A, const __half* __restrict__ Bm,
    float* __restrict__ C, __half* __restrict__ C16,
    __half* __restrict__ Crope, const float2* __restrict__ tab, float scl,
    int nheads, int M, int N, int K, int mode) {
  extern __shared__ char smem[];
  const uint32_t sb = smem_to_u32(smem);
  const int tid = threadIdx.x, wid = tid >> 5, lane = tid & 31;
  const int wm = wid >> 1, wn = wid & 1;
  const int m0 = blockIdx.y * BM, n0 = blockIdx.x * BN;
  const __half* pA = A + (size_t)m0 * K;
  const __half* pB = Bm + (size_t)n0 * K;

  float acc[4][8][4];
#pragma unroll
  for (int f = 0; f < 4; f++)
#pragma unroll
    for (int n = 0; n < 8; n++)
#pragma unroll
      for (int e = 0; e < 4; e++) acc[f][n][e] = 0.f;

  auto load_stage = [&](int k0, int buf) {
    const uint32_t base = sb + buf * FSTAGEB;
#pragma unroll
    for (int i = 0; i < 8; i++) {
      const int idx = i * 128 + tid;
      const int r = idx >> 3, c = idx & 7;
      const uint32_t d = base + r * 128u + ((uint32_t)(c ^ (r & 7)) << 4);
      const size_t go = (size_t)r * K + k0 + c * 8;
      cp16(d, pA + go);
      cp16(d + FTILEB, pB + go);
    }
    CP_COMMIT();
  };

  const int S = K / FBK;
  load_stage(0, 0);
  load_stage(FBK, 1);

  const int rowa = wm * 64 + (lane & 15);
  const int rowb = wn * 64 + (lane & 7) + ((lane >> 4) << 3);

  for (int s = 0; s < S; s++) {
    const int buf = s % 3;
    if (s == S - 1) CP_WAIT0(); else CP_WAIT1();
    __syncthreads();
    if (s + 2 < S) load_stage((s + 2) * FBK, (s + 2) % 3);
    const uint32_t abase = sb + buf * FSTAGEB;
    const uint32_t bbase = abase + FTILEB;
#pragma unroll
    for (int ks = 0; ks < 4; ks++) {
      uint32_t ah[4][4], bh[4][4];
      const int ca = 2 * ks + (lane >> 4);
      const int cb = 2 * ks + ((lane >> 3) & 1);
#pragma unroll
      for (int f = 0; f < 4; f++) {
        const int rr = rowa + f * 16;
        ldsm4(abase + rr * 128u + ((uint32_t)(ca ^ (rr & 7)) << 4), ah[f]);
      }
#pragma unroll
      for (int p = 0; p < 4; p++) {
        const int rr = rowb + p * 16;
        ldsm4(bbase + rr * 128u + ((uint32_t)(cb ^ (rr & 7)) << 4), bh[p]);
      }
#pragma unroll
      for (int f = 0; f < 4; f++)
#pragma unroll
        for (int n = 0; n < 8; n++)
          mma16816h(acc[f][n], ah[f], &bh[n >> 1][(n & 1) * 2]);
    }
  }

  const bool rope = (mode == 3) || (mode == 4 && n0 < 512);
  if (rope) {
    // stage accumulators to smem (fp32, row stride 132) then rope per row
    float* st = (float*)smem;
    __syncthreads();  // all warps done reading stage buffers
#pragma unroll
    for (int f = 0; f < 4; f++) {
      const int r0 = wm * 64 + f * 16 + (lane >> 2);
#pragma unroll
      for (int n = 0; n < 8; n++) {
        const int c = wn * 64 + n * 8 + (lane & 3) * 2;
        *(float2*)&st[r0 * 132 + c] = make_float2(acc[f][n][0], acc[f][n][1]);
        *(float2*)&st[(r0 + 8) * 132 + c] =
            make_float2(acc[f][n][2], acc[f][n][3]);
      }
    }
    __syncthreads();
    const int r = tid;  // 128 threads, one row each
    const int gRow = m0 + r;
    const int l = gRow & (L - 1);
    const int h = n0 >> 7;
    __half* dst = Crope + ((size_t)gRow * nheads + h) * 128;
    const float2* tl = tab + (size_t)l * 64;
    const float* row = st + r * 132;
#pragma unroll
    for (int d = 0; d < 64; d += 2) {
      const float2 cs0 = tl[d], cs1 = tl[d + 1];
      const float a0 = row[d], a1 = row[d + 1];
      const float b0 = row[d + 64], b1 = row[d + 65];
      *(__half2*)&dst[d] = __floats2half2_rn((a0 * cs0.x - b0 * cs0.y) * scl,
                                             (a1 * cs1.x - b1 * cs1.y) * scl);
      *(__half2*)&dst[d + 64] = __floats2half2_rn(
          (b0 * cs0.x + a0 * cs0.y) * scl, (b1 * cs1.x + a1 * cs1.y) * scl);
    }
    return;
  }

#pragma unroll
  for (int f = 0; f < 4; f++) {
    const int row = m0 + wm * 64 + f * 16 + (lane >> 2);
#pragma unroll
    for (int n = 0; n < 8; n++) {
      const int col = n0 + wn * 64 + n * 8 + (lane & 3) * 2;
      if (mode == 0) {
        *(float2*)&C[(size_t)row * N + col] =
            make_float2(acc[f][n][0], acc[f][n][1]);
        *(float2*)&C[(size_t)(row + 8) * N + col] =
            make_float2(acc[f][n][2], acc[f][n][3]);
      } else if (mode == 1) {
        *(__half2*)&C16[(size_t)row * N + col] =
            __floats2half2_rn(acc[f][n][0], acc[f][n][1]);
        *(__half2*)&C16[(size_t)(row + 8) * N + col] =
            __floats2half2_rn(acc[f][n][2], acc[f][n][3]);
      } else {  // mode 4 V half: fp16, row stride 512
        const int cv = col - 512;
        *(__half2*)&C16[(size_t)row * 512 + cv] =
            __floats2half2_rn(acc[f][n][0], acc[f][n][1]);
        *(__half2*)&C16[(size_t)(row + 8) * 512 + cv] =
            __floats2half2_rn(acc[f][n][2], acc[f][n][3]);
      }
    }
  }
}

// ======================= fp16 flash attention =======================
// Balanced pairing; Q in smem; 2 CTAs/SM; log2-domain softmax (ex2.approx).
// Q pre-scaled by SCALE*log2e. Single launch over both batches.
#define AQ 128
#define NQT (L / AQ)
#define AKT 32
#define ASMEM (3 * 16384 + 32768) /* 3 KV stages + Q region = 80KB */

__global__ __launch_bounds__(256, 2) void attn_mma(
    const __half* __restrict__ Qf, const __half* __restrict__ Kf,
    const __half* __restrict__ Vf, const int* __restrict__ mask,
    __half* __restrict__ Yf) {
  extern __shared__ char smem[];
  const uint32_t sb = smem_to_u32(smem);
  const uint32_t sbQ = sb + 3 * 16384u;
  const int pair = blockIdx.x;
  const int h = blockIdx.y, b = blockIdx.z;
  const int hkv = h >> 2;
  const int tid = threadIdx.x, w = tid >> 5, lane = tid & 31;

  const __half* khg = Kf + ((size_t)(b * L) * NKV + hkv) * 128;
  const __half* vhg = Vf + ((size_t)(b * L) * NKV + hkv) * 128;
  const int* mrow = mask + b * L;

  const int rbB = (lane & 7) + ((lane >> 4) << 3);
  const int rvB = (lane & 7) + (((lane >> 3) & 1) << 3);
  const int rowa = w * 16 + (lane & 15);
  const uint32_t qrow = sbQ + (uint32_t)rowa * 256u;

  for (int half = 0; half < 2; half++) {
    const int qt = half == 0 ? (NQT - 1 - pair) : pair;  // heavy first
    const int q0 = qt * AQ;
    __syncthreads();  // prior half fully done with smem

    // ---- stage Q into persistent smem region ----
    {
      const __half* qg = Qf + ((size_t)(b * L + q0) * NH + h) * 128;
#pragma unroll
      for (int i = 0; i < 8; i++) {
        const int idx = i * 256 + tid;
        const int r = idx >> 4, c = idx & 15;
        const uint32_t d = sbQ + r * 256u + ((uint32_t)(c ^ (r & 7)) << 4);
        cp16(d, qg + (size_t)r * (NH * 128) + c * 8);
      }
      CP_COMMIT();
      CP_WAIT0();
      __syncthreads();
    }

    float o[16][4];
#pragma unroll
    for (int nf = 0; nf < 16; nf++)
#pragma unroll
      for (int e = 0; e < 4; e++) o[nf][e] = 0.f;
    float m2[2] = {-1e30f, -1e30f}, ls[2] = {0.f, 0.f};

    auto load_kv = [&](int t, int buf) {
      const int k0 = t * AKT;
      const uint32_t base = sb + buf * 16384u;
#pragma unroll
      for (int i = 0; i < 2; i++) {
        const int idx = i * 256 + tid;
        const int r = idx >> 4, c = idx & 15;
        const uint32_t d = base + r * 256u + ((uint32_t)(c ^ (r & 7)) << 4);
        const size_t go = (size_t)(k0 + r) * (NKV * 128) + c * 8;
        cp16(d, khg + go);
        cp16(d + 8192u, vhg + go);
      }
      CP_COMMIT();
    };

    const int nkt = qt * 4 + 4;
    load_kv(0, 0);
    if (nkt > 1) load_kv(1, 1);

    const int qa = q0 + w * 16 + (lane >> 2);
    const int qb = qa + 8;

    for (int kt = 0; kt < nkt; kt++) {
      const int buf = kt % 3;
      const int k0 = kt * AKT;
      if (kt >= nkt - 1) CP_WAIT0(); else CP_WAIT1();
      __syncthreads();
      if (kt + 2 < nkt) load_kv(kt + 2, (kt + 2) % 3);

      if (k0 <= q0 + w * 16 + 15) {
        const uint32_t kb = sb + buf * 16384u;
        float s[4][4];
#pragma unroll
        for (int n = 0; n < 4; n++)
#pragma unroll
          for (int e = 0; e < 4; e++) s[n][e] = 0.f;

#pragma unroll
        for (int kd = 0; kd < 8; kd++) {
          const int ca = 2 * kd + (lane >> 4);
          uint32_t qf4[4];
          ldsm4(qrow + ((uint32_t)(ca ^ (rowa & 7)) << 4), qf4);
          const int cb = 2 * kd + ((lane >> 3) & 1);
          const uint32_t b0a =
              kb + (uint32_t)rbB * 256u + ((uint32_t)(cb ^ (rbB & 7)) << 4);
          uint32_t bh0[4], bh1[4];
          ldsm4(b0a, bh0);
          ldsm4(b0a + 16u * 256u, bh1);
#pragma unroll
          for (int n = 0; n < 4; n++) {
            const uint32_t* bp =
                (n < 2) ? &bh0[(n & 1) * 2] : &bh1[(n & 1) * 2];
            mma16816h(s[n], qf4, bp);
          }
        }

        float rmax[2] = {-1e30f, -1e30f};
#pragma unroll
        for (int n = 0; n < 4; n++) {
          const int col = k0 + n * 8 + (lane & 3) * 2;
          const bool mk0 = mrow[col] > 0, mk1 = mrow[col + 1] > 0;
          s[n][0] = (mk0 && col <= qa) ? s[n][0] : -1e30f;
          s[n][1] = (mk1 && col + 1 <= qa) ? s[n][1] : -1e30f;
          s[n][2] = (mk0 && col <= qb) ? s[n][2] : -1e30f;
          s[n][3] = (mk1 && col + 1 <= qb) ? s[n][3] : -1e30f;
          rmax[0] = fmaxf(rmax[0], fmaxf(s[n][0], s[n][1]));
          rmax[1] = fmaxf(rmax[1], fmaxf(s[n][2], s[n][3]));
        }
#pragma unroll
        for (int off = 1; off <= 2; off <<= 1) {
          rmax[0] = fmaxf(rmax[0], __shfl_xor_sync(0xffffffffu, rmax[0], off));
          rmax[1] = fmaxf(rmax[1], __shfl_xor_sync(0xffffffffu, rmax[1], off));
        }
        const float mn0 = fmaxf(m2[0], rmax[0]);
        const float mn1 = fmaxf(m2[1], rmax[1]);
        const bool noup =
            __all_sync(0xffffffffu, (mn0 == m2[0]) & (mn1 == m2[1]));
        if (!noup) {
          const float al0 = ex2(m2[0] - mn0);
          const float al1 = ex2(m2[1] - mn1);
          ls[0] *= al0;
          ls[1] *= al1;
#pragma unroll
          for (int nf = 0; nf < 16; nf++) {
            o[nf][0] *= al0;
            o[nf][1] *= al0;
            o[nf][2] *= al1;
            o[nf][3] *= al1;
          }
          m2[0] = mn0;
          m2[1] = mn1;
        }
        float ps0 = 0.f, ps1 = 0.f;
#pragma unroll
        for (int n = 0; n < 4; n++) {
          s[n][0] = ex2(s[n][0] - m2[0]);
          s[n][1] = ex2(s[n][1] - m2[0]);
          s[n][2] = ex2(s[n][2] - m2[1]);
          s[n][3] = ex2(s[n][3] - m2[1]);
          ps0 += s[n][0] + s[n][1];
          ps1 += s[n][2] + s[n][3];
        }
#pragma unroll
        for (int off = 1; off <= 2; off <<= 1) {
          ps0 += __shfl_xor_sync(0xffffffffu, ps0, off);
          ps1 += __shfl_xor_sync(0xffffffffu, ps1, off);
        }
        ls[0] += ps0;
        ls[1] += ps1;

        uint32_t pa[2][4];
#pragma unroll
        for (int ks = 0; ks < 2; ks++) {
          pa[ks][0] = pk2h(s[2 * ks][0], s[2 * ks][1]);
          pa[ks][1] = pk2h(s[2 * ks][2], s[2 * ks][3]);
          pa[ks][2] = pk2h(s[2 * ks + 1][0], s[2 * ks + 1][1]);
          pa[ks][3] = pk2h(s[2 * ks + 1][2], s[2 * ks + 1][3]);
        }

        const uint32_t vb = kb + 8192u;
#pragma unroll
        for (int ks = 0; ks < 2; ks++) {
          const int rowv = 16 * ks + rvB;
#pragma unroll
          for (int j = 0; j < 8; j++) {
            const int cv = 2 * j + (lane >> 4);
            uint32_t vhf[4];
            ldsm4t(vb + (uint32_t)rowv * 256u +
                       ((uint32_t)(cv ^ (rowv & 7)) << 4),
                   vhf);
            mma16816h(o[2 * j], pa[ks], &vhf[0]);
            mma16816h(o[2 * j + 1], pa[ks], &vhf[2]);
          }
        }
      }
    }

    const float inv0 = 1.f / ls[0], inv1 = 1.f / ls[1];
    const size_t rA = (size_t)(b * L + qa) * (size_t)HID + h * 128;
    const size_t rB = rA + (size_t)8 * HID;
#pragma unroll
    for (int nf = 0; nf < 16; nf++) {
      const int d = nf * 8 + (lane & 3) * 2;
      *(__half2*)&Yf[rA + d] =
          __floats2half2_rn(o[nf][0] * inv0, o[nf][1] * inv0);
      *(__half2*)&Yf[rB + d] =
          __floats2half2_rn(o[nf][2] * inv1, o[nf][3] * inv1);
    }
  }
}

// ======================= launch =======================
extern "C" void kernel_launch(void* const* d_in, const int* in_sizes, int n_in,
                              void* d_out, int out_size) {
  const float* x = (const float*)d_in[0];
  const float* Wq = (const float*)d_in[1];
  const float* Wc = (const float*)d_in[2];
  const float* Wk = (const float*)d_in[3];
  const float* Wv = (const float*)d_in[4];
  const float* Wo = (const float*)d_in[5];
  const int* mask = (const int*)d_in[6];
  float* out = (float*)d_out;

  float2* tab;
  cudaGetSymbolAddress((void**)&tab, g_tab);
  __half *xf, *cf, *qf, *kf, *vf, *yf, *wqf, *wcf, *wkvf, *wof;
  cudaGetSymbolAddress((void**)&xf, g_xf);
  cudaGetSymbolAddress((void**)&cf, g_cf);
  cudaGetSymbolAddress((void**)&qf, g_Qf);
  cudaGetSymbolAddress((void**)&kf, g_Kf);
  cudaGetSymbolAddress((void**)&vf, g_Vf);
  cudaGetSymbolAddress((void**)&yf, g_Yf);
  cudaGetSymbolAddress((void**)&wqf, g_Wqt_f);
  cudaGetSymbolAddress((void**)&wcf, g_Wct_f);
  cudaGetSymbolAddress((void**)&wkvf, g_Wkvt_f);
  cudaGetSymbolAddress((void**)&wof, g_Wot_f);

  const int M = B * L;  // 4096

  cudaFuncSetAttribute(mma_gemm_f16, cudaFuncAttributeMaxDynamicSharedMemorySize,
                       GSMEM_F16);
  cudaFuncSetAttribute(attn_mma, cudaFuncAttributeMaxDynamicSharedMemorySize,
                       ASMEM);

  // ---- main stream: shared preprocessing ----
  rope_tab_kernel<<<(L * 64 + 255) / 256, 256>>>(tab);                       // 0
  split_f16_kernel<<<(M * HID / 4 + 255) / 256, 256>>>(x, xf, M * HID / 4);  // 1
  tsplit_f16_kernel<<<dim3((NH * HDIM) / 32, HID / 32), 256>>>(
      Wq, wqf, HID, NH * HDIM);                                              // 2

  // ---- fork: side stream does Q projection + fused RoPE ----
  cudaEventRecord(g_ctx.e0, 0);
  cudaStreamWaitEvent(g_ctx.side, g_ctx.e0, 0);
  mma_gemm_f16<<<dim3((NH * HDIM) / BN, M / BM), 128, GSMEM_F16, g_ctx.side>>>(
      xf, wqf, nullptr, nullptr, qf, tab, SCALE_L2E, NH, M, NH * HDIM, HID,
      3);  // 3 <- profiled slot
  cudaEventRecord(g_ctx.e1, g_ctx.side);

  // ---- main stream: C -> K/V chain ----
  tsplit_f16_kernel<<<dim3(LAT / 32, HID / 32), 256>>>(Wc, wcf, HID, LAT);
  tsplit_f16_kernel<<<dim3((NKV * HDIM) / 32, LAT / 32), 256>>>(
      Wk, wkvf, LAT, NKV * HDIM);  // rows 0..511
  tsplit_f16_kernel<<<dim3((NKV * HDIM) / 32, LAT / 32), 256>>>(
      Wv, wkvf + (size_t)NKV * HDIM * LAT, LAT, NKV * HDIM);  // rows 512..1023
  mma_gemm_f16<<<dim3(LAT / BN, M / BM), 128, GSMEM_F16>>>(
      xf, wcf, nullptr, cf, nullptr, nullptr, 1.0f, 0, M, LAT, HID, 1);
  mma_gemm_f16<<<dim3((2 * NKV * HDIM) / BN, M / BM), 128, GSMEM_F16>>>(
      cf, wkvf, nullptr, vf, kf, tab, 1.0f, NKV, M, 2 * NKV * HDIM, LAT, 4);
  tsplit_f16_kernel<<<dim3(HID / 32, (NH * HDIM) / 32), 256>>>(
      Wo, wof, NH * HDIM, HID);

  // ---- join, attention (single balanced wave), output projection ----
  cudaStreamWaitEvent(0, g_ctx.e1, 0);
  attn_mma<<<dim3(NQT / 2, NH, B), 256, ASMEM>>>(qf, kf, vf, mask, yf);
  mma_gemm_f16<<<dim3(HID / BN, M / BM), 128, GSMEM_F16>>>(
      yf, wof, out, nullptr, nullptr, nullptr, 1.0f, 0, M, HID, HID, 0);
}

// round 14
// speedup vs baseline: 1.1172x; 1.1172x over previous
#include <cuda_runtime.h>
#include <cuda_fp16.h>
#include <cstdint>
#include <math.h>

#define B 2
#define L 2048
#define HID 2048
#define NH 16
#define NKV 4
#define HDIM 128
#define LAT 512
#define SCALE 0.08838834764831845f /* 1/sqrt(128) */
#define SCALE_L2E 0.1275216702398461f /* SCALE * log2(e) */

// ======================= helpers =======================
__device__ __forceinline__ uint32_t smem_to_u32(const void* p) {
  uint32_t a;
  asm("{ .reg .u64 t; cvta.to.shared.u64 t, %1; cvt.u32.u64 %0, t; }"
      : "=r"(a) : "l"(p));
  return a;
}
__device__ __forceinline__ void cp16(uint32_t dst, const void* src) {
  asm volatile("cp.async.cg.shared.global [%0], [%1], 16;" ::"r"(dst), "l"(src));
}
#define CP_COMMIT() asm volatile("cp.async.commit_group;" ::: "memory")
#define CP_WAIT1() asm volatile("cp.async.wait_group 1;" ::: "memory")
#define CP_WAIT0() asm volatile("cp.async.wait_group 0;" ::: "memory")

__device__ __forceinline__ void ldsm4(uint32_t addr, uint32_t* r) {
  asm volatile("ldmatrix.sync.aligned.m8n8.x4.shared.b16 {%0,%1,%2,%3}, [%4];"
               : "=r"(r[0]), "=r"(r[1]), "=r"(r[2]), "=r"(r[3]) : "r"(addr));
}
__device__ __forceinline__ void ldsm4t(uint32_t addr, uint32_t* r) {
  asm volatile(
      "ldmatrix.sync.aligned.m8n8.x4.trans.shared.b16 {%0,%1,%2,%3}, [%4];"
      : "=r"(r[0]), "=r"(r[1]), "=r"(r[2]), "=r"(r[3]) : "r"(addr));
}
__device__ __forceinline__ void mma16816h(float* c, const uint32_t* a,
                                          const uint32_t* b) {
  asm volatile(
      "mma.sync.aligned.m16n8k16.row.col.f32.f16.f16.f32 "
      "{%0,%1,%2,%3}, {%4,%5,%6,%7}, {%8,%9}, {%0,%1,%2,%3};"
      : "+f"(c[0]), "+f"(c[1]), "+f"(c[2]), "+f"(c[3])
      : "r"(a[0]), "r"(a[1]), "r"(a[2]), "r"(a[3]), "r"(b[0]), "r"(b[1]));
}
__device__ __forceinline__ uint32_t pk2h(float lo, float hi) {
  __half2 h = __floats2half2_rn(lo, hi);
  return *(uint32_t*)&h;
}
__device__ __forceinline__ float ex2(float x) {
  float y;
  asm("ex2.approx.f32 %0, %1;" : "=f"(y) : "f"(x));
  return y;
}

// ======================= scratch =======================
__device__ float g_Q[(size_t)B * L * NH * HDIM];
__device__ float g_K[(size_t)B * L * NKV * HDIM];
__device__ float2 g_tab[(size_t)L * 64];  // RoPE cos/sin table

__device__ __half g_xf[(size_t)B * L * HID];
__device__ __half g_cf[(size_t)B * L * LAT];
__device__ __half g_Qf[(size_t)B * L * NH * HDIM];
__device__ __half g_Kf[(size_t)B * L * NKV * HDIM];
__device__ __half g_Vf[(size_t)B * L * NKV * HDIM];
__device__ __half g_Yf[(size_t)B * L * HID];
__device__ __half g_Wqt_f[(size_t)NH * HDIM * HID];
__device__ __half g_Wct_f[(size_t)LAT * HID];
__device__ __half g_Wkvt_f[(size_t)2 * NKV * HDIM * LAT];  // [Wk; Wv] rows
__device__ __half g_Wot_f[(size_t)HID * NH * HDIM];

// ======================= stream context (created pre-main) ==============
namespace {
struct Ctx {
  cudaStream_t side;
  cudaEvent_t e0, e1, e2;
  Ctx() {
    cudaStreamCreateWithFlags(&side, cudaStreamNonBlocking);
    cudaEventCreateWithFlags(&e0, cudaEventDisableTiming);
    cudaEventCreateWithFlags(&e1, cudaEventDisableTiming);
    cudaEventCreateWithFlags(&e2, cudaEventDisableTiming);
  }
};
Ctx g_ctx;
}  // namespace

// ======================= preprocessing =======================
__global__ void split_f16_kernel(const float* __restrict__ s,
                                 __half* __restrict__ f, int n4) {
  int i = blockIdx.x * blockDim.x + threadIdx.x;
  if (i >= n4) return;
  float4 v = ((const float4*)s)[i];
  ((__half2*)f)[2 * i] = __floats2half2_rn(v.x, v.y);
  ((__half2*)f)[2 * i + 1] = __floats2half2_rn(v.z, v.w);
}

// W[K,N] fp32 -> Wt[N,K] fp16
__global__ __launch_bounds__(256) void tsplit_f16_kernel(
    const float* __restrict__ W, __half* __restrict__ f, int K, int N) {
  __shared__ float t[32][33];
  const int n0 = blockIdx.x * 32, k0 = blockIdx.y * 32;
  const int tx = threadIdx.x & 31, ty = threadIdx.x >> 5;
#pragma unroll
  for (int i = 0; i < 32; i += 8)
    t[ty + i][tx] = W[(size_t)(k0 + ty + i) * N + n0 + tx];
  __syncthreads();
#pragma unroll
  for (int i = 0; i < 32; i += 8)
    f[(size_t)(n0 + ty + i) * K + k0 + tx] = __float2half(t[tx][ty + i]);
}

// RoPE table: tab[l][hf] = (cos, sin)(l * 10000^(-hf/64)), double precision
__global__ void rope_tab_kernel(float2* __restrict__ tab) {
  int i = blockIdx.x * blockDim.x + threadIdx.x;
  if (i >= L * 64) return;
  const int hf = i & 63;
  const int l = i >> 6;
  const double inv = exp(-(double)hf * 0.14391156831212788);
  const double fr = (double)l * inv;
  tab[i] = make_float2((float)cos(fr), (float)sin(fr));
}

// RoPE fp32 -> fp16 via table (optionally pre-scaled), layout [B, L, H, 128]
__global__ void rope_f16_kernel(const float* __restrict__ t,
                                const float2* __restrict__ tab,
                                __half* __restrict__ f, int H, int total,
                                float scl) {
  int i = blockIdx.x * blockDim.x + threadIdx.x;
  if (i >= total) return;
  const int hf = i & 63;
  const int h = (i >> 6) % H;
  const int bl = i / (64 * H);
  const int l = bl & (L - 1);
  const float2 cs = tab[l * 64 + hf];
  const size_t base = ((size_t)bl * H + h) * HDIM;
  const float a = t[base + hf];
  const float b2 = t[base + hf + 64];
  f[base + hf] = __float2half((a * cs.x - b2 * cs.y) * scl);
  f[base + hf + 64] = __float2half((b2 * cs.x + a * cs.y) * scl);
}

// ======================= fp16 GEMM: 64x64 warp tiles =======================
// C[M,N] = A[M,K] @ B[N,K]^T, fp16 in, fp32 accum. 4 warps/CTA, 3-stage.
// mode 0: fp32 out; mode 1: fp16 out; mode 2: KV split.
#define BM 128
#define BN 128
#define FBK 64
#define FTILEB 16384u
#define FSTAGEB 32768u
#define GSMEM_F16 (3 * 32768)

__global__ __launch_bounds__(128, 2) void mma_gemm_f16(
    const __half* __restrict__ A, const __half* __restrict__ Bm,
    float* __restrict__ C, __half* __restrict__ C16, int M, int N, int K,
    int mode) {
  extern __shared__ char smem[];
  const uint32_t sb = smem_to_u32(smem);
  const int tid = threadIdx.x, wid = tid >> 5, lane = tid & 31;
  const int wm = wid >> 1, wn = wid & 1;
  const int m0 = blockIdx.y * BM, n0 = blockIdx.x * BN;
  const __half* pA = A + (size_t)m0 * K;
  const __half* pB = Bm + (size_t)n0 * K;

  float acc[4][8][4];
#pragma unroll
  for (int f = 0; f < 4; f++)
#pragma unroll
    for (int n = 0; n < 8; n++)
#pragma unroll
      for (int e = 0; e < 4; e++) acc[f][n][e] = 0.f;

  auto load_stage = [&](int k0, int buf) {
    const uint32_t base = sb + buf * FSTAGEB;
#pragma unroll
    for (int i = 0; i < 8; i++) {
      const int idx = i * 128 + tid;
      const int r = idx >> 3, c = idx & 7;
      const uint32_t d = base + r * 128u + ((uint32_t)(c ^ (r & 7)) << 4);
      const size_t go = (size_t)r * K + k0 + c * 8;
      cp16(d, pA + go);
      cp16(d + FTILEB, pB + go);
    }
    CP_COMMIT();
  };

  const int S = K / FBK;
  load_stage(0, 0);
  load_stage(FBK, 1);

  const int rowa = wm * 64 + (lane & 15);
  const int rowb = wn * 64 + (lane & 7) + ((lane >> 4) << 3);

  for (int s = 0; s < S; s++) {
    const int buf = s % 3;
    if (s == S - 1) CP_WAIT0(); else CP_WAIT1();
    __syncthreads();
    if (s + 2 < S) load_stage((s + 2) * FBK, (s + 2) % 3);
    const uint32_t abase = sb + buf * FSTAGEB;
    const uint32_t bbase = abase + FTILEB;
#pragma unroll
    for (int ks = 0; ks < 4; ks++) {
      uint32_t ah[4][4], bh[4][4];
      const int ca = 2 * ks + (lane >> 4);
      const int cb = 2 * ks + ((lane >> 3) & 1);
#pragma unroll
      for (int f = 0; f < 4; f++) {
        const int rr = rowa + f * 16;
        ldsm4(abase + rr * 128u + ((uint32_t)(ca ^ (rr & 7)) << 4), ah[f]);
      }
#pragma unroll
      for (int p = 0; p < 4; p++) {
        const int rr = rowb + p * 16;
        ldsm4(bbase + rr * 128u + ((uint32_t)(cb ^ (rr & 7)) << 4), bh[p]);
      }
#pragma unroll
      for (int f = 0; f < 4; f++)
#pragma unroll
        for (int n = 0; n < 8; n++)
          mma16816h(acc[f][n], ah[f], &bh[n >> 1][(n & 1) * 2]);
    }
  }

#pragma unroll
  for (int f = 0; f < 4; f++) {
    const int row = m0 + wm * 64 + f * 16 + (lane >> 2);
#pragma unroll
    for (int n = 0; n < 8; n++) {
      const int col = n0 + wn * 64 + n * 8 + (lane & 3) * 2;
      if (mode == 0) {
        *(float2*)&C[(size_t)row * N + col] =
            make_float2(acc[f][n][0], acc[f][n][1]);
        *(float2*)&C[(size_t)(row + 8) * N + col] =
            make_float2(acc[f][n][2], acc[f][n][3]);
      } else if (mode == 1) {
        *(__half2*)&C16[(size_t)row * N + col] =
            __floats2half2_rn(acc[f][n][0], acc[f][n][1]);
        *(__half2*)&C16[(size_t)(row + 8) * N + col] =
            __floats2half2_rn(acc[f][n][2], acc[f][n][3]);
      } else {
        if (col < 512) {  // K -> fp32 (RoPE input), row stride 512
          *(float2*)&C[(size_t)row * 512 + col] =
              make_float2(acc[f][n][0], acc[f][n][1]);
          *(float2*)&C[(size_t)(row + 8) * 512 + col] =
              make_float2(acc[f][n][2], acc[f][n][3]);
        } else {  // V -> fp16, row stride 512
          const int cv = col - 512;
          *(__half2*)&C16[(size_t)row * 512 + cv] =
              __floats2half2_rn(acc[f][n][0], acc[f][n][1]);
          *(__half2*)&C16[(size_t)(row + 8) * 512 + cv] =
              __floats2half2_rn(acc[f][n][2], acc[f][n][3]);
        }
      }
    }
  }
}

// ======================= fp16 flash attention =======================
// Balanced pairing; Q in smem; 2 CTAs/SM; log2-domain softmax (ex2.approx).
// Q pre-scaled by SCALE*log2e in rope. Single launch over both batches.
#define AQ 128
#define NQT (L / AQ)
#define AKT 32
#define ASMEM (3 * 16384 + 32768) /* 3 KV stages + Q region = 80KB */

__global__ __launch_bounds__(256, 2) void attn_mma(
    const __half* __restrict__ Qf, const __half* __restrict__ Kf,
    const __half* __restrict__ Vf, const int* __restrict__ mask,
    __half* __restrict__ Yf) {
  extern __shared__ char smem[];
  const uint32_t sb = smem_to_u32(smem);
  const uint32_t sbQ = sb + 3 * 16384u;
  const int pair = blockIdx.x;
  const int h = blockIdx.y, b = blockIdx.z;
  const int hkv = h >> 2;
  const int tid = threadIdx.x, w = tid >> 5, lane = tid & 31;

  const __half* khg = Kf + ((size_t)(b * L) * NKV + hkv) * 128;
  const __half* vhg = Vf + ((size_t)(b * L) * NKV + hkv) * 128;
  const int* mrow = mask + b * L;

  const int rbB = (lane & 7) + ((lane >> 4) << 3);
  const int rvB = (lane & 7) + (((lane >> 3) & 1) << 3);
  const int rowa = w * 16 + (lane & 15);
  const uint32_t qrow = sbQ + (uint32_t)rowa * 256u;

  for (int half = 0; half < 2; half++) {
    const int qt = half == 0 ? (NQT - 1 - pair) : pair;  // heavy first
    const int q0 = qt * AQ;
    __syncthreads();  // prior half fully done with smem

    // ---- stage Q into persistent smem region ----
    {
      const __half* qg = Qf + ((size_t)(b * L + q0) * NH + h) * 128;
#pragma unroll
      for (int i = 0; i < 8; i++) {
        const int idx = i * 256 + tid;
        const int r = idx >> 4, c = idx & 15;
        const uint32_t d = sbQ + r * 256u + ((uint32_t)(c ^ (r & 7)) << 4);
        cp16(d, qg + (size_t)r * (NH * 128) + c * 8);
      }
      CP_COMMIT();
      CP_WAIT0();
      __syncthreads();
    }

    float o[16][4];
#pragma unroll
    for (int nf = 0; nf < 16; nf++)
#pragma unroll
      for (int e = 0; e < 4; e++) o[nf][e] = 0.f;
    float m2[2] = {-1e30f, -1e30f}, ls[2] = {0.f, 0.f};

    auto load_kv = [&](int t, int buf) {
      const int k0 = t * AKT;
      const uint32_t base = sb + buf * 16384u;
#pragma unroll
      for (int i = 0; i < 2; i++) {
        const int idx = i * 256 + tid;
        const int r = idx >> 4, c = idx & 15;
        const uint32_t d = base + r * 256u + ((uint32_t)(c ^ (r & 7)) << 4);
        const size_t go = (size_t)(k0 + r) * (NKV * 128) + c * 8;
        cp16(d, khg + go);
        cp16(d + 8192u, vhg + go);
      }
      CP_COMMIT();
    };

    const int nkt = qt * 4 + 4;
    load_kv(0, 0);
    if (nkt > 1) load_kv(1, 1);

    const int qa = q0 + w * 16 + (lane >> 2);
    const int qb = qa + 8;

    for (int kt = 0; kt < nkt; kt++) {
      const int buf = kt % 3;
      const int k0 = kt * AKT;
      if (kt >= nkt - 1) CP_WAIT0(); else CP_WAIT1();
      __syncthreads();
      if (kt + 2 < nkt) load_kv(kt + 2, (kt + 2) % 3);

      if (k0 <= q0 + w * 16 + 15) {
        const uint32_t kb = sb + buf * 16384u;
        float s[4][4];
#pragma unroll
        for (int n = 0; n < 4; n++)
#pragma unroll
          for (int e = 0; e < 4; e++) s[n][e] = 0.f;

#pragma unroll
        for (int kd = 0; kd < 8; kd++) {
          const int ca = 2 * kd + (lane >> 4);
          uint32_t qf4[4];
          ldsm4(qrow + ((uint32_t)(ca ^ (rowa & 7)) << 4), qf4);
          const int cb = 2 * kd + ((lane >> 3) & 1);
          const uint32_t b0a =
              kb + (uint32_t)rbB * 256u + ((uint32_t)(cb ^ (rbB & 7)) << 4);
          uint32_t bh0[4], bh1[4];
          ldsm4(b0a, bh0);
          ldsm4(b0a + 16u * 256u, bh1);
#pragma unroll
          for (int n = 0; n < 4; n++) {
            const uint32_t* bp =
                (n < 2) ? &bh0[(n & 1) * 2] : &bh1[(n & 1) * 2];
            mma16816h(s[n], qf4, bp);
          }
        }

        float rmax[2] = {-1e30f, -1e30f};
#pragma unroll
        for (int n = 0; n < 4; n++) {
          const int col = k0 + n * 8 + (lane & 3) * 2;
          const bool mk0 = mrow[col] > 0, mk1 = mrow[col + 1] > 0;
          s[n][0] = (mk0 && col <= qa) ? s[n][0] : -1e30f;
          s[n][1] = (mk1 && col + 1 <= qa) ? s[n][1] : -1e30f;
          s[n][2] = (mk0 && col <= qb) ? s[n][2] : -1e30f;
          s[n][3] = (mk1 && col + 1 <= qb) ? s[n][3] : -1e30f;
          rmax[0] = fmaxf(rmax[0], fmaxf(s[n][0], s[n][1]));
          rmax[1] = fmaxf(rmax[1], fmaxf(s[n][2], s[n][3]));
        }
#pragma unroll
        for (int off = 1; off <= 2; off <<= 1) {
          rmax[0] = fmaxf(rmax[0], __shfl_xor_sync(0xffffffffu, rmax[0], off));
          rmax[1] = fmaxf(rmax[1], __shfl_xor_sync(0xffffffffu, rmax[1], off));
        }
        const float mn0 = fmaxf(m2[0], rmax[0]);
        const float mn1 = fmaxf(m2[1], rmax[1]);
        const bool noup =
            __all_sync(0xffffffffu, (mn0 == m2[0]) & (mn1 == m2[1]));
        if (!noup) {
          const float al0 = ex2(m2[0] - mn0);
          const float al1 = ex2(m2[1] - mn1);
          ls[0] *= al0;
          ls[1] *= al1;
#pragma unroll
          for (int nf = 0; nf < 16; nf++) {
            o[nf][0] *= al0;
            o[nf][1] *= al0;
            o[nf][2] *= al1;
            o[nf][3] *= al1;
          }
          m2[0] = mn0;
          m2[1] = mn1;
        }
        float ps0 = 0.f, ps1 = 0.f;
#pragma unroll
        for (int n = 0; n < 4; n++) {
          s[n][0] = ex2(s[n][0] - m2[0]);
          s[n][1] = ex2(s[n][1] - m2[0]);
          s[n][2] = ex2(s[n][2] - m2[1]);
          s[n][3] = ex2(s[n][3] - m2[1]);
          ps0 += s[n][0] + s[n][1];
          ps1 += s[n][2] + s[n][3];
        }
#pragma unroll
        for (int off = 1; off <= 2; off <<= 1) {
          ps0 += __shfl_xor_sync(0xffffffffu, ps0, off);
          ps1 += __shfl_xor_sync(0xffffffffu, ps1, off);
        }
        ls[0] += ps0;
        ls[1] += ps1;

        uint32_t pa[2][4];
#pragma unroll
        for (int ks = 0; ks < 2; ks++) {
          pa[ks][0] = pk2h(s[2 * ks][0], s[2 * ks][1]);
          pa[ks][1] = pk2h(s[2 * ks][2], s[2 * ks][3]);
          pa[ks][2] = pk2h(s[2 * ks + 1][0], s[2 * ks + 1][1]);
          pa[ks][3] = pk2h(s[2 * ks + 1][2], s[2 * ks + 1][3]);
        }

        const uint32_t vb = kb + 8192u;
#pragma unroll
        for (int ks = 0; ks < 2; ks++) {
          const int rowv = 16 * ks + rvB;
#pragma unroll
          for (int j = 0; j < 8; j++) {
            const int cv = 2 * j + (lane >> 4);
            uint32_t vhf[4];
            ldsm4t(vb + (uint32_t)rowv * 256u +
                       ((uint32_t)(cv ^ (rowv & 7)) << 4),
                   vhf);
            mma16816h(o[2 * j], pa[ks], &vhf[0]);
            mma16816h(o[2 * j + 1], pa[ks], &vhf[2]);
          }
        }
      }
    }

    const float inv0 = 1.f / ls[0], inv1 = 1.f / ls[1];
    const size_t rA = (size_t)(b * L + qa) * (size_t)HID + h * 128;
    const size_t rB = rA + (size_t)8 * HID;
#pragma unroll
    for (int nf = 0; nf < 16; nf++) {
      const int d = nf * 8 + (lane & 3) * 2;
      *(__half2*)&Yf[rA + d] =
          __floats2half2_rn(o[nf][0] * inv0, o[nf][1] * inv0);
      *(__half2*)&Yf[rB + d] =
          __floats2half2_rn(o[nf][2] * inv1, o[nf][3] * inv1);
    }
  }
}

// ======================= launch =======================
extern "C" void kernel_launch(void* const* d_in, const int* in_sizes, int n_in,
                              void* d_out, int out_size) {
  const float* x = (const float*)d_in[0];
  const float* Wq = (const float*)d_in[1];
  const float* Wc = (const float*)d_in[2];
  const float* Wk = (const float*)d_in[3];
  const float* Wv = (const float*)d_in[4];
  const float* Wo = (const float*)d_in[5];
  const int* mask = (const int*)d_in[6];
  float* out = (float*)d_out;

  float *Qp, *Kp;
  float2* tab;
  cudaGetSymbolAddress((void**)&Qp, g_Q);
  cudaGetSymbolAddress((void**)&Kp, g_K);
  cudaGetSymbolAddress((void**)&tab, g_tab);
  __half *xf, *cf, *qf, *kf, *vf, *yf, *wqf, *wcf, *wkvf, *wof;
  cudaGetSymbolAddress((void**)&xf, g_xf);
  cudaGetSymbolAddress((void**)&cf, g_cf);
  cudaGetSymbolAddress((void**)&qf, g_Qf);
  cudaGetSymbolAddress((void**)&kf, g_Kf);
  cudaGetSymbolAddress((void**)&vf, g_Vf);
  cudaGetSymbolAddress((void**)&yf, g_Yf);
  cudaGetSymbolAddress((void**)&wqf, g_Wqt_f);
  cudaGetSymbolAddress((void**)&wcf, g_Wct_f);
  cudaGetSymbolAddress((void**)&wkvf, g_Wkvt_f);
  cudaGetSymbolAddress((void**)&wof, g_Wot_f);

  const int M = B * L;  // 4096

  cudaFuncSetAttribute(mma_gemm_f16, cudaFuncAttributeMaxDynamicSharedMemorySize,
                       GSMEM_F16);
  cudaFuncSetAttribute(attn_mma, cudaFuncAttributeMaxDynamicSharedMemorySize,
                       ASMEM);

  // ---- main: rope table + x split; side: Wq transpose (independent) ----
  rope_tab_kernel<<<(L * 64 + 255) / 256, 256>>>(tab);                       // 0
  split_f16_kernel<<<(M * HID / 4 + 255) / 256, 256>>>(x, xf, M * HID / 4);  // 1
  tsplit_f16_kernel<<<dim3((NH * HDIM) / 32, HID / 32), 256, 0, g_ctx.side>>>(
      Wq, wqf, HID, NH * HDIM);                                              // 2

  // ---- fork: side waits for xf (+tab), then Q projection + RoPE Q ----
  cudaEventRecord(g_ctx.e0, 0);
  cudaStreamWaitEvent(g_ctx.side, g_ctx.e0, 0);
  mma_gemm_f16<<<dim3((NH * HDIM) / BN, M / BM), 128, GSMEM_F16, g_ctx.side>>>(
      xf, wqf, Qp, nullptr, M, NH * HDIM, HID, 0);  // 3 <- profiled slot
  const int totQ = B * L * NH * 64;
  rope_f16_kernel<<<(totQ + 255) / 256, 256, 0, g_ctx.side>>>(
      Qp, tab, qf, NH, totQ, SCALE_L2E);
  cudaEventRecord(g_ctx.e1, g_ctx.side);

  // ---- main stream: C -> K/V chain ----
  tsplit_f16_kernel<<<dim3(LAT / 32, HID / 32), 256>>>(Wc, wcf, HID, LAT);
  tsplit_f16_kernel<<<dim3((NKV * HDIM) / 32, LAT / 32), 256>>>(
      Wk, wkvf, LAT, NKV * HDIM);  // rows 0..511
  tsplit_f16_kernel<<<dim3((NKV * HDIM) / 32, LAT / 32), 256>>>(
      Wv, wkvf + (size_t)NKV * HDIM * LAT, LAT, NKV * HDIM);  // rows 512..1023
  mma_gemm_f16<<<dim3(LAT / BN, M / BM), 128, GSMEM_F16>>>(
      xf, wcf, nullptr, cf, M, LAT, HID, 1);
  mma_gemm_f16<<<dim3((2 * NKV * HDIM) / BN, M / BM), 128, GSMEM_F16>>>(
      cf, wkvf, Kp, vf, M, 2 * NKV * HDIM, LAT, 2);
  const int totK = B * L * NKV * 64;
  rope_f16_kernel<<<(totK + 255) / 256, 256>>>(Kp, tab, kf, NKV, totK, 1.0f);
  tsplit_f16_kernel<<<dim3(HID / 32, (NH * HDIM) / 32), 256>>>(
      Wo, wof, NH * HDIM, HID);

  // ---- join, attention (single balanced wave), output projection ----
  cudaStreamWaitEvent(0, g_ctx.e1, 0);
  attn_mma<<<dim3(NQT / 2, NH, B), 256, ASMEM>>>(qf, kf, vf, mask, yf);
  mma_gemm_f16<<<dim3(HID / BN, M / BM), 128, GSMEM_F16>>>(
      yf, wof, out, nullptr, M, HID, HID, 0);
}

// round 15
// speedup vs baseline: 1.1180x; 1.0007x over previous
#include <cuda_runtime.h>
#include <cuda_fp16.h>
#include <cstdint>
#include <math.h>

#define B 2
#define L 2048
#define HID 2048
#define NH 16
#define NKV 4
#define HDIM 128
#define LAT 512
#define SCALE 0.08838834764831845f /* 1/sqrt(128) */
#define SCALE_L2E 0.1275216702398461f /* SCALE * log2(e) */

// ======================= helpers =======================
__device__ __forceinline__ uint32_t smem_to_u32(const void* p) {
  uint32_t a;
  asm("{ .reg .u64 t; cvta.to.shared.u64 t, %1; cvt.u32.u64 %0, t; }"
      : "=r"(a) : "l"(p));
  return a;
}
__device__ __forceinline__ void cp16(uint32_t dst, const void* src) {
  asm volatile("cp.async.cg.shared.global [%0], [%1], 16;" ::"r"(dst), "l"(src));
}
#define CP_COMMIT() asm volatile("cp.async.commit_group;" ::: "memory")
#define CP_WAIT1() asm volatile("cp.async.wait_group 1;" ::: "memory")
#define CP_WAIT0() asm volatile("cp.async.wait_group 0;" ::: "memory")

__device__ __forceinline__ void ldsm4(uint32_t addr, uint32_t* r) {
  asm volatile("ldmatrix.sync.aligned.m8n8.x4.shared.b16 {%0,%1,%2,%3}, [%4];"
               : "=r"(r[0]), "=r"(r[1]), "=r"(r[2]), "=r"(r[3]) : "r"(addr));
}
__device__ __forceinline__ void ldsm4t(uint32_t addr, uint32_t* r) {
  asm volatile(
      "ldmatrix.sync.aligned.m8n8.x4.trans.shared.b16 {%0,%1,%2,%3}, [%4];"
      : "=r"(r[0]), "=r"(r[1]), "=r"(r[2]), "=r"(r[3]) : "r"(addr));
}
__device__ __forceinline__ void mma16816h(float* c, const uint32_t* a,
                                          const uint32_t* b) {
  asm volatile(
      "mma.sync.aligned.m16n8k16.row.col.f32.f16.f16.f32 "
      "{%0,%1,%2,%3}, {%4,%5,%6,%7}, {%8,%9}, {%0,%1,%2,%3};"
      : "+f"(c[0]), "+f"(c[1]), "+f"(c[2]), "+f"(c[3])
      : "r"(a[0]), "r"(a[1]), "r"(a[2]), "r"(a[3]), "r"(b[0]), "r"(b[1]));
}
__device__ __forceinline__ uint32_t pk2h(float lo, float hi) {
  __half2 h = __floats2half2_rn(lo, hi);
  return *(uint32_t*)&h;
}
__device__ __forceinline__ float ex2(float x) {
  float y;
  asm("ex2.approx.f32 %0, %1;" : "=f"(y) : "f"(x));
  return y;
}

// ======================= scratch =======================
__device__ float g_Q[(size_t)B * L * NH * HDIM];
__device__ float g_K[(size_t)B * L * NKV * HDIM];
__device__ float2 g_tab[(size_t)L * 64];  // RoPE cos/sin table

__device__ __half g_xf[(size_t)B * L * HID];
__device__ __half g_cf[(size_t)B * L * LAT];
__device__ __half g_Qf[(size_t)B * L * NH * HDIM];
__device__ __half g_Kf[(size_t)B * L * NKV * HDIM];
__device__ __half g_Vf[(size_t)B * L * NKV * HDIM];
__device__ __half g_Yf[(size_t)B * L * HID];
__device__ __half g_Wqt_f[(size_t)NH * HDIM * HID];
__device__ __half g_Wct_f[(size_t)LAT * HID];
__device__ __half g_Wkvt_f[(size_t)2 * NKV * HDIM * LAT];  // [Wk; Wv] rows
__device__ __half g_Wot_f[(size_t)HID * NH * HDIM];

// ======================= stream context (created pre-main) ==============
namespace {
struct Ctx {
  cudaStream_t side;
  cudaEvent_t e0, e1;
  Ctx() {
    cudaStreamCreateWithFlags(&side, cudaStreamNonBlocking);
    cudaEventCreateWithFlags(&e0, cudaEventDisableTiming);
    cudaEventCreateWithFlags(&e1, cudaEventDisableTiming);
  }
};
Ctx g_ctx;
}  // namespace

// ======================= preprocessing =======================
__global__ void split_f16_kernel(const float* __restrict__ s,
                                 __half* __restrict__ f, int n4) {
  int i = blockIdx.x * blockDim.x + threadIdx.x;
  if (i >= n4) return;
  float4 v = ((const float4*)s)[i];
  ((__half2*)f)[2 * i] = __floats2half2_rn(v.x, v.y);
  ((__half2*)f)[2 * i + 1] = __floats2half2_rn(v.z, v.w);
}

// W[K,N] fp32 -> Wt[N,K] fp16
__global__ __launch_bounds__(256) void tsplit_f16_kernel(
    const float* __restrict__ W, __half* __restrict__ f, int K, int N) {
  __shared__ float t[32][33];
  const int n0 = blockIdx.x * 32, k0 = blockIdx.y * 32;
  const int tx = threadIdx.x & 31, ty = threadIdx.x >> 5;
#pragma unroll
  for (int i = 0; i < 32; i += 8)
    t[ty + i][tx] = W[(size_t)(k0 + ty + i) * N + n0 + tx];
  __syncthreads();
#pragma unroll
  for (int i = 0; i < 32; i += 8)
    f[(size_t)(n0 + ty + i) * K + k0 + tx] = __float2half(t[tx][ty + i]);
}

// RoPE table: tab[l][hf] = (cos, sin)(l * 10000^(-hf/64)), double precision
__global__ void rope_tab_kernel(float2* __restrict__ tab) {
  int i = blockIdx.x * blockDim.x + threadIdx.x;
  if (i >= L * 64) return;
  const int hf = i & 63;
  const int l = i >> 6;
  const double inv = exp(-(double)hf * 0.14391156831212788);
  const double fr = (double)l * inv;
  tab[i] = make_float2((float)cos(fr), (float)sin(fr));
}

// RoPE fp32 -> fp16 via table (optionally pre-scaled), layout [B, L, H, 128]
__global__ void rope_f16_kernel(const float* __restrict__ t,
                                const float2* __restrict__ tab,
                                __half* __restrict__ f, int H, int total,
                                float scl) {
  int i = blockIdx.x * blockDim.x + threadIdx.x;
  if (i >= total) return;
  const int hf = i & 63;
  const int h = (i >> 6) % H;
  const int bl = i / (64 * H);
  const int l = bl & (L - 1);
  const float2 cs = tab[l * 64 + hf];
  const size_t base = ((size_t)bl * H + h) * HDIM;
  const float a = t[base + hf];
  const float b2 = t[base + hf + 64];
  f[base + hf] = __float2half((a * cs.x - b2 * cs.y) * scl);
  f[base + hf + 64] = __float2half((b2 * cs.x + a * cs.y) * scl);
}

// ======================= fp16 GEMM: 64x64 warp tiles =======================
// C[M,N] = A[M,K] @ B[N,K]^T, fp16 in, fp32 accum. 4 warps/CTA, 3-stage.
// mode 0: fp32 out; mode 1: fp16 out; mode 2: KV split.
#define BM 128
#define BN 128
#define FBK 64
#define FTILEB 16384u
#define FSTAGEB 32768u
#define GSMEM_F16 (3 * 32768)

__global__ __launch_bounds__(128, 2) void mma_gemm_f16(
    const __half* __restrict__ A, const __half* __restrict__ Bm,
    float* __restrict__ C, __half* __restrict__ C16, int M, int N, int K,
    int mode) {
  extern __shared__ char smem[];
  const uint32_t sb = smem_to_u32(smem);
  const int tid = threadIdx.x, wid = tid >> 5, lane = tid & 31;
  const int wm = wid >> 1, wn = wid & 1;
  const int m0 = blockIdx.y * BM, n0 = blockIdx.x * BN;
  const __half* pA = A + (size_t)m0 * K;
  const __half* pB = Bm + (size_t)n0 * K;

  float acc[4][8][4];
#pragma unroll
  for (int f = 0; f < 4; f++)
#pragma unroll
    for (int n = 0; n < 8; n++)
#pragma unroll
      for (int e = 0; e < 4; e++) acc[f][n][e] = 0.f;

  auto load_stage = [&](int k0, int buf) {
    const uint32_t base = sb + buf * FSTAGEB;
#pragma unroll
    for (int i = 0; i < 8; i++) {
      const int idx = i * 128 + tid;
      const int r = idx >> 3, c = idx & 7;
      const uint32_t d = base + r * 128u + ((uint32_t)(c ^ (r & 7)) << 4);
      const size_t go = (size_t)r * K + k0 + c * 8;
      cp16(d, pA + go);
      cp16(d + FTILEB, pB + go);
    }
    CP_COMMIT();
  };

  const int S = K / FBK;
  load_stage(0, 0);
  load_stage(FBK, 1);

  const int rowa = wm * 64 + (lane & 15);
  const int rowb = wn * 64 + (lane & 7) + ((lane >> 4) << 3);

  for (int s = 0; s < S; s++) {
    const int buf = s % 3;
    if (s == S - 1) CP_WAIT0(); else CP_WAIT1();
    __syncthreads();
    if (s + 2 < S) load_stage((s + 2) * FBK, (s + 2) % 3);
    const uint32_t abase = sb + buf * FSTAGEB;
    const uint32_t bbase = abase + FTILEB;
#pragma unroll
    for (int ks = 0; ks < 4; ks++) {
      uint32_t ah[4][4], bh[4][4];
      const int ca = 2 * ks + (lane >> 4);
      const int cb = 2 * ks + ((lane >> 3) & 1);
#pragma unroll
      for (int f = 0; f < 4; f++) {
        const int rr = rowa + f * 16;
        ldsm4(abase + rr * 128u + ((uint32_t)(ca ^ (rr & 7)) << 4), ah[f]);
      }
#pragma unroll
      for (int p = 0; p < 4; p++) {
        const int rr = rowb + p * 16;
        ldsm4(bbase + rr * 128u + ((uint32_t)(cb ^ (rr & 7)) << 4), bh[p]);
      }
#pragma unroll
      for (int f = 0; f < 4; f++)
#pragma unroll
        for (int n = 0; n < 8; n++)
          mma16816h(acc[f][n], ah[f], &bh[n >> 1][(n & 1) * 2]);
    }
  }

#pragma unroll
  for (int f = 0; f < 4; f++) {
    const int row = m0 + wm * 64 + f * 16 + (lane >> 2);
#pragma unroll
    for (int n = 0; n < 8; n++) {
      const int col = n0 + wn * 64 + n * 8 + (lane & 3) * 2;
      if (mode == 0) {
        *(float2*)&C[(size_t)row * N + col] =
            make_float2(acc[f][n][0], acc[f][n][1]);
        *(float2*)&C[(size_t)(row + 8) * N + col] =
            make_float2(acc[f][n][2], acc[f][n][3]);
      } else if (mode == 1) {
        *(__half2*)&C16[(size_t)row * N + col] =
            __floats2half2_rn(acc[f][n][0], acc[f][n][1]);
        *(__half2*)&C16[(size_t)(row + 8) * N + col] =
            __floats2half2_rn(acc[f][n][2], acc[f][n][3]);
      } else {
        if (col < 512) {  // K -> fp32 (RoPE input), row stride 512
          *(float2*)&C[(size_t)row * 512 + col] =
              make_float2(acc[f][n][0], acc[f][n][1]);
          *(float2*)&C[(size_t)(row + 8) * 512 + col] =
              make_float2(acc[f][n][2], acc[f][n][3]);
        } else {  // V -> fp16, row stride 512
          const int cv = col - 512;
          *(__half2*)&C16[(size_t)row * 512 + cv] =
              __floats2half2_rn(acc[f][n][0], acc[f][n][1]);
          *(__half2*)&C16[(size_t)(row + 8) * 512 + cv] =
              __floats2half2_rn(acc[f][n][2], acc[f][n][3]);
        }
      }
    }
  }
}

// ======================= fp16 flash attention =======================
// Balanced pairing; Q in smem; 2 CTAs/SM; log2-domain softmax (ex2.approx).
// Q pre-scaled by SCALE*log2e. 64-key KV stages (2-stage pipeline) processed
// as two 32-key sub-tiles -> half the barriers, identical numerics/registers.
#define AQ 128
#define NQT (L / AQ)
#define AKT 64
#define ASMEM (2 * 32768 + 32768) /* 2 KV stages (K16K+V16K each) + Q = 96KB */

__global__ __launch_bounds__(256, 2) void attn_mma(
    const __half* __restrict__ Qf, const __half* __restrict__ Kf,
    const __half* __restrict__ Vf, const int* __restrict__ mask,
    __half* __restrict__ Yf) {
  extern __shared__ char smem[];
  const uint32_t sb = smem_to_u32(smem);
  const uint32_t sbQ = sb + 2 * 32768u;
  const int pair = blockIdx.x;
  const int h = blockIdx.y, b = blockIdx.z;
  const int hkv = h >> 2;
  const int tid = threadIdx.x, w = tid >> 5, lane = tid & 31;

  const __half* khg = Kf + ((size_t)(b * L) * NKV + hkv) * 128;
  const __half* vhg = Vf + ((size_t)(b * L) * NKV + hkv) * 128;
  const int* mrow = mask + b * L;

  const int rbB = (lane & 7) + ((lane >> 4) << 3);
  const int rvB = (lane & 7) + (((lane >> 3) & 1) << 3);
  const int rowa = w * 16 + (lane & 15);
  const uint32_t qrow = sbQ + (uint32_t)rowa * 256u;

  for (int half = 0; half < 2; half++) {
    const int qt = half == 0 ? (NQT - 1 - pair) : pair;  // heavy first
    const int q0 = qt * AQ;
    __syncthreads();  // prior half fully done with smem

    // ---- stage Q into persistent smem region ----
    {
      const __half* qg = Qf + ((size_t)(b * L + q0) * NH + h) * 128;
#pragma unroll
      for (int i = 0; i < 8; i++) {
        const int idx = i * 256 + tid;
        const int r = idx >> 4, c = idx & 15;
        const uint32_t d = sbQ + r * 256u + ((uint32_t)(c ^ (r & 7)) << 4);
        cp16(d, qg + (size_t)r * (NH * 128) + c * 8);
      }
      CP_COMMIT();
      CP_WAIT0();
      __syncthreads();
    }

    float o[16][4];
#pragma unroll
    for (int nf = 0; nf < 16; nf++)
#pragma unroll
      for (int e = 0; e < 4; e++) o[nf][e] = 0.f;
    float m2[2] = {-1e30f, -1e30f}, ls[2] = {0.f, 0.f};

    // 64-key stage: K (64x128 fp16 = 16KB) at base, V at base+16KB
    auto load_kv = [&](int t, int buf) {
      const int k0 = t * AKT;
      const uint32_t base = sb + buf * 32768u;
#pragma unroll
      for (int i = 0; i < 4; i++) {
        const int idx = i * 256 + tid;
        const int r = idx >> 4, c = idx & 15;
        const uint32_t d = base + r * 256u + ((uint32_t)(c ^ (r & 7)) << 4);
        const size_t go = (size_t)(k0 + r) * (NKV * 128) + c * 8;
        cp16(d, khg + go);
        cp16(d + 16384u, vhg + go);
      }
      CP_COMMIT();
    };

    const int nkt = qt * 2 + 2;  // 64-key tiles covering [0, q0+128)
    load_kv(0, 0);

    const int qa = q0 + w * 16 + (lane >> 2);
    const int qb = qa + 8;
    const int wmax = q0 + w * 16 + 15;

    for (int kt = 0; kt < nkt; kt++) {
      const int buf = kt & 1;
      CP_WAIT0();
      __syncthreads();  // data visible + other buffer fully consumed
      if (kt + 1 < nkt) load_kv(kt + 1, (kt + 1) & 1);
      const uint32_t kb = sb + buf * 32768u;

#pragma unroll
      for (int sub = 0; sub < 2; sub++) {
        const int k0 = kt * AKT + sub * 32;
        if (k0 > wmax) continue;
        const uint32_t ksub = kb + (uint32_t)sub * 8192u;  // 32 rows * 256B

        float s[4][4];
#pragma unroll
        for (int n = 0; n < 4; n++)
#pragma unroll
          for (int e = 0; e < 4; e++) s[n][e] = 0.f;

#pragma unroll
        for (int kd = 0; kd < 8; kd++) {
          const int ca = 2 * kd + (lane >> 4);
          uint32_t qf4[4];
          ldsm4(qrow + ((uint32_t)(ca ^ (rowa & 7)) << 4), qf4);
          const int cb = 2 * kd + ((lane >> 3) & 1);
          const uint32_t b0a =
              ksub + (uint32_t)rbB * 256u + ((uint32_t)(cb ^ (rbB & 7)) << 4);
          uint32_t bh0[4], bh1[4];
          ldsm4(b0a, bh0);
          ldsm4(b0a + 16u * 256u, bh1);
#pragma unroll
          for (int n = 0; n < 4; n++) {
            const uint32_t* bp =
                (n < 2) ? &bh0[(n & 1) * 2] : &bh1[(n & 1) * 2];
            mma16816h(s[n], qf4, bp);
          }
        }

        float rmax[2] = {-1e30f, -1e30f};
#pragma unroll
        for (int n = 0; n < 4; n++) {
          const int col = k0 + n * 8 + (lane & 3) * 2;
          const bool mk0 = mrow[col] > 0, mk1 = mrow[col + 1] > 0;
          s[n][0] = (mk0 && col <= qa) ? s[n][0] : -1e30f;
          s[n][1] = (mk1 && col + 1 <= qa) ? s[n][1] : -1e30f;
          s[n][2] = (mk0 && col <= qb) ? s[n][2] : -1e30f;
          s[n][3] = (mk1 && col + 1 <= qb) ? s[n][3] : -1e30f;
          rmax[0] = fmaxf(rmax[0], fmaxf(s[n][0], s[n][1]));
          rmax[1] = fmaxf(rmax[1], fmaxf(s[n][2], s[n][3]));
        }
#pragma unroll
        for (int off = 1; off <= 2; off <<= 1) {
          rmax[0] = fmaxf(rmax[0], __shfl_xor_sync(0xffffffffu, rmax[0], off));
          rmax[1] = fmaxf(rmax[1], __shfl_xor_sync(0xffffffffu, rmax[1], off));
        }
        const float mn0 = fmaxf(m2[0], rmax[0]);
        const float mn1 = fmaxf(m2[1], rmax[1]);
        const bool noup =
            __all_sync(0xffffffffu, (mn0 == m2[0]) & (mn1 == m2[1]));
        if (!noup) {
          const float al0 = ex2(m2[0] - mn0);
          const float al1 = ex2(m2[1] - mn1);
          ls[0] *= al0;
          ls[1] *= al1;
#pragma unroll
          for (int nf = 0; nf < 16; nf++) {
            o[nf][0] *= al0;
            o[nf][1] *= al0;
            o[nf][2] *= al1;
            o[nf][3] *= al1;
          }
          m2[0] = mn0;
          m2[1] = mn1;
        }
        float ps0 = 0.f, ps1 = 0.f;
#pragma unroll
        for (int n = 0; n < 4; n++) {
          s[n][0] = ex2(s[n][0] - m2[0]);
          s[n][1] = ex2(s[n][1] - m2[0]);
          s[n][2] = ex2(s[n][2] - m2[1]);
          s[n][3] = ex2(s[n][3] - m2[1]);
          ps0 += s[n][0] + s[n][1];
          ps1 += s[n][2] + s[n][3];
        }
#pragma unroll
        for (int off = 1; off <= 2; off <<= 1) {
          ps0 += __shfl_xor_sync(0xffffffffu, ps0, off);
          ps1 += __shfl_xor_sync(0xffffffffu, ps1, off);
        }
        ls[0] += ps0;
        ls[1] += ps1;

        uint32_t pa[2][4];
#pragma unroll
        for (int ks = 0; ks < 2; ks++) {
          pa[ks][0] = pk2h(s[2 * ks][0], s[2 * ks][1]);
          pa[ks][1] = pk2h(s[2 * ks][2], s[2 * ks][3]);
          pa[ks][2] = pk2h(s[2 * ks + 1][0], s[2 * ks + 1][1]);
          pa[ks][3] = pk2h(s[2 * ks + 1][2], s[2 * ks + 1][3]);
        }

        const uint32_t vb = kb + 16384u + (uint32_t)sub * 8192u;
#pragma unroll
        for (int ks = 0; ks < 2; ks++) {
          const int rowv = 16 * ks + rvB;
#pragma unroll
          for (int j = 0; j < 8; j++) {
            const int cv = 2 * j + (lane >> 4);
            uint32_t vhf[4];
            ldsm4t(vb + (uint32_t)rowv * 256u +
                       ((uint32_t)(cv ^ (rowv & 7)) << 4),
                   vhf);
            mma16816h(o[2 * j], pa[ks], &vhf[0]);
            mma16816h(o[2 * j + 1], pa[ks], &vhf[2]);
          }
        }
      }
    }

    const float inv0 = 1.f / ls[0], inv1 = 1.f / ls[1];
    const size_t rA = (size_t)(b * L + qa) * (size_t)HID + h * 128;
    const size_t rB = rA + (size_t)8 * HID;
#pragma unroll
    for (int nf = 0; nf < 16; nf++) {
      const int d = nf * 8 + (lane & 3) * 2;
      *(__half2*)&Yf[rA + d] =
          __floats2half2_rn(o[nf][0] * inv0, o[nf][1] * inv0);
      *(__half2*)&Yf[rB + d] =
          __floats2half2_rn(o[nf][2] * inv1, o[nf][3] * inv1);
    }
  }
}

// ======================= launch =======================
extern "C" void kernel_launch(void* const* d_in, const int* in_sizes, int n_in,
                              void* d_out, int out_size) {
  const float* x = (const float*)d_in[0];
  const float* Wq = (const float*)d_in[1];
  const float* Wc = (const float*)d_in[2];
  const float* Wk = (const float*)d_in[3];
  const float* Wv = (const float*)d_in[4];
  const float* Wo = (const float*)d_in[5];
  const int* mask = (const int*)d_in[6];
  float* out = (float*)d_out;

  float *Qp, *Kp;
  float2* tab;
  cudaGetSymbolAddress((void**)&Qp, g_Q);
  cudaGetSymbolAddress((void**)&Kp, g_K);
  cudaGetSymbolAddress((void**)&tab, g_tab);
  __half *xf, *cf, *qf, *kf, *vf, *yf, *wqf, *wcf, *wkvf, *wof;
  cudaGetSymbolAddress((void**)&xf, g_xf);
  cudaGetSymbolAddress((void**)&cf, g_cf);
  cudaGetSymbolAddress((void**)&qf, g_Qf);
  cudaGetSymbolAddress((void**)&kf, g_Kf);
  cudaGetSymbolAddress((void**)&vf, g_Vf);
  cudaGetSymbolAddress((void**)&yf, g_Yf);
  cudaGetSymbolAddress((void**)&wqf, g_Wqt_f);
  cudaGetSymbolAddress((void**)&wcf, g_Wct_f);
  cudaGetSymbolAddress((void**)&wkvf, g_Wkvt_f);
  cudaGetSymbolAddress((void**)&wof, g_Wot_f);

  const int M = B * L;  // 4096

  cudaFuncSetAttribute(mma_gemm_f16, cudaFuncAttributeMaxDynamicSharedMemorySize,
                       GSMEM_F16);
  cudaFuncSetAttribute(attn_mma, cudaFuncAttributeMaxDynamicSharedMemorySize,
                       ASMEM);

  // ---- main: rope table + x split; side: Wq transpose (independent) ----
  rope_tab_kernel<<<(L * 64 + 255) / 256, 256>>>(tab);                       // 0
  split_f16_kernel<<<(M * HID / 4 + 255) / 256, 256>>>(x, xf, M * HID / 4);  // 1
  tsplit_f16_kernel<<<dim3((NH * HDIM) / 32, HID / 32), 256, 0, g_ctx.side>>>(
      Wq, wqf, HID, NH * HDIM);                                              // 2

  // ---- fork: side waits for xf (+tab), then Q projection + RoPE Q ----
  cudaEventRecord(g_ctx.e0, 0);
  cudaStreamWaitEvent(g_ctx.side, g_ctx.e0, 0);
  mma_gemm_f16<<<dim3((NH * HDIM) / BN, M / BM), 128, GSMEM_F16, g_ctx.side>>>(
      xf, wqf, Qp, nullptr, M, NH * HDIM, HID, 0);  // 3 <- profiled slot
  const int totQ = B * L * NH * 64;
  rope_f16_kernel<<<(totQ + 255) / 256, 256, 0, g_ctx.side>>>(
      Qp, tab, qf, NH, totQ, SCALE_L2E);
  cudaEventRecord(g_ctx.e1, g_ctx.side);

  // ---- main stream: C -> K/V chain ----
  tsplit_f16_kernel<<<dim3(LAT / 32, HID / 32), 256>>>(Wc, wcf, HID, LAT);
  tsplit_f16_kernel<<<dim3((NKV * HDIM) / 32, LAT / 32), 256>>>(
      Wk, wkvf, LAT, NKV * HDIM);  // rows 0..511
  tsplit_f16_kernel<<<dim3((NKV * HDIM) / 32, LAT / 32), 256>>>(
      Wv, wkvf + (size_t)NKV * HDIM * LAT, LAT, NKV * HDIM);  // rows 512..1023
  mma_gemm_f16<<<dim3(LAT / BN, M / BM), 128, GSMEM_F16>>>(
      xf, wcf, nullptr, cf, M, LAT, HID, 1);
  mma_gemm_f16<<<dim3((2 * NKV * HDIM) / BN, M / BM), 128, GSMEM_F16>>>(
      cf, wkvf, Kp, vf, M, 2 * NKV * HDIM, LAT, 2);
  const int totK = B * L * NKV * 64;
  rope_f16_kernel<<<(totK + 255) / 256, 256>>>(Kp, tab, kf, NKV, totK, 1.0f);
  tsplit_f16_kernel<<<dim3(HID / 32, (NH * HDIM) / 32), 256>>>(
      Wo, wof, NH * HDIM, HID);

  // ---- join, attention (single balanced wave), output projection ----
  cudaStreamWaitEvent(0, g_ctx.e1, 0);
  attn_mma<<<dim3(NQT / 2, NH, B), 256, ASMEM>>>(qf, kf, vf, mask, yf);
  mma_gemm_f16<<<dim3(HID / BN, M / BM), 128, GSMEM_F16>>>(
      yf, wof, out, nullptr, M, HID, HID, 0);
}

// round 16
// speedup vs baseline: 1.1302x; 1.0109x over previous
#include <cuda_runtime.h>
#include <cuda_fp16.h>
#include <cstdint>
#include <math.h>

#define B 2
#define L 2048
#define HID 2048
#define NH 16
#define NKV 4
#define HDIM 128
#define LAT 512
#define SCALE 0.08838834764831845f /* 1/sqrt(128) */
#define SCALE_L2E 0.1275216702398461f /* SCALE * log2(e) */

// ======================= helpers =======================
__device__ __forceinline__ uint32_t smem_to_u32(const void* p) {
  uint32_t a;
  asm("{ .reg .u64 t; cvta.to.shared.u64 t, %1; cvt.u32.u64 %0, t; }"
      : "=r"(a) : "l"(p));
  return a;
}
__device__ __forceinline__ void cp16(uint32_t dst, const void* src) {
  asm volatile("cp.async.cg.shared.global [%0], [%1], 16;" ::"r"(dst), "l"(src));
}
#define CP_COMMIT() asm volatile("cp.async.commit_group;" ::: "memory")
#define CP_WAIT1() asm volatile("cp.async.wait_group 1;" ::: "memory")
#define CP_WAIT0() asm volatile("cp.async.wait_group 0;" ::: "memory")

__device__ __forceinline__ void ldsm4(uint32_t addr, uint32_t* r) {
  asm volatile("ldmatrix.sync.aligned.m8n8.x4.shared.b16 {%0,%1,%2,%3}, [%4];"
               : "=r"(r[0]), "=r"(r[1]), "=r"(r[2]), "=r"(r[3]) : "r"(addr));
}
__device__ __forceinline__ void ldsm4t(uint32_t addr, uint32_t* r) {
  asm volatile(
      "ldmatrix.sync.aligned.m8n8.x4.trans.shared.b16 {%0,%1,%2,%3}, [%4];"
      : "=r"(r[0]), "=r"(r[1]), "=r"(r[2]), "=r"(r[3]) : "r"(addr));
}
__device__ __forceinline__ void mma16816h(float* c, const uint32_t* a,
                                          const uint32_t* b) {
  asm volatile(
      "mma.sync.aligned.m16n8k16.row.col.f32.f16.f16.f32 "
      "{%0,%1,%2,%3}, {%4,%5,%6,%7}, {%8,%9}, {%0,%1,%2,%3};"
      : "+f"(c[0]), "+f"(c[1]), "+f"(c[2]), "+f"(c[3])
      : "r"(a[0]), "r"(a[1]), "r"(a[2]), "r"(a[3]), "r"(b[0]), "r"(b[1]));
}
__device__ __forceinline__ uint32_t pk2h(float lo, float hi) {
  __half2 h = __floats2half2_rn(lo, hi);
  return *(uint32_t*)&h;
}
__device__ __forceinline__ float ex2(float x) {
  float y;
  asm("ex2.approx.f32 %0, %1;" : "=f"(y) : "f"(x));
  return y;
}

// ======================= scratch =======================
__device__ float g_K[(size_t)B * L * NKV * HDIM];
__device__ float2 g_tab[(size_t)L * 64];  // RoPE cos/sin table

__device__ __half g_xf[(size_t)B * L * HID];
__device__ __half g_cf[(size_t)B * L * LAT];
__device__ __half g_Qf[(size_t)B * L * NH * HDIM];
__device__ __half g_Kf[(size_t)B * L * NKV * HDIM];
__device__ __half g_Vf[(size_t)B * L * NKV * HDIM];
__device__ __half g_Yf[(size_t)B * L * HID];  // pre-rope Q, then attention out
__device__ __half g_Wqt_f[(size_t)NH * HDIM * HID];
__device__ __half g_Wct_f[(size_t)LAT * HID];
__device__ __half g_Wkvt_f[(size_t)2 * NKV * HDIM * LAT];  // [Wk; Wv] rows
__device__ __half g_Wot_f[(size_t)HID * NH * HDIM];

// ======================= stream context (created pre-main) ==============
namespace {
struct Ctx {
  cudaStream_t side;
  cudaEvent_t e0, e1, e2;
  Ctx() {
    cudaStreamCreateWithFlags(&side, cudaStreamNonBlocking);
    cudaEventCreateWithFlags(&e0, cudaEventDisableTiming);
    cudaEventCreateWithFlags(&e1, cudaEventDisableTiming);
    cudaEventCreateWithFlags(&e2, cudaEventDisableTiming);
  }
};
Ctx g_ctx;
}  // namespace

// ======================= preprocessing =======================
__global__ void split_f16_kernel(const float* __restrict__ s,
                                 __half* __restrict__ f, int n4) {
  int i = blockIdx.x * blockDim.x + threadIdx.x;
  if (i >= n4) return;
  float4 v = ((const float4*)s)[i];
  ((__half2*)f)[2 * i] = __floats2half2_rn(v.x, v.y);
  ((__half2*)f)[2 * i + 1] = __floats2half2_rn(v.z, v.w);
}

// W[K,N] fp32 -> Wt[N,K] fp16
__global__ __launch_bounds__(256) void tsplit_f16_kernel(
    const float* __restrict__ W, __half* __restrict__ f, int K, int N) {
  __shared__ float t[32][33];
  const int n0 = blockIdx.x * 32, k0 = blockIdx.y * 32;
  const int tx = threadIdx.x & 31, ty = threadIdx.x >> 5;
#pragma unroll
  for (int i = 0; i < 32; i += 8)
    t[ty + i][tx] = W[(size_t)(k0 + ty + i) * N + n0 + tx];
  __syncthreads();
#pragma unroll
  for (int i = 0; i < 32; i += 8)
    f[(size_t)(n0 + ty + i) * K + k0 + tx] = __float2half(t[tx][ty + i]);
}

// RoPE table: tab[l][hf] = (cos, sin)(l * 10000^(-hf/64)), double precision
__global__ void rope_tab_kernel(float2* __restrict__ tab) {
  int i = blockIdx.x * blockDim.x + threadIdx.x;
  if (i >= L * 64) return;
  const int hf = i & 63;
  const int l = i >> 6;
  const double inv = exp(-(double)hf * 0.14391156831212788);
  const double fr = (double)l * inv;
  tab[i] = make_float2((float)cos(fr), (float)sin(fr));
}

// RoPE fp32 -> fp16 via table (optionally pre-scaled), layout [B, L, H, 128]
__global__ void rope_f16_kernel(const float* __restrict__ t,
                                const float2* __restrict__ tab,
                                __half* __restrict__ f, int H, int total,
                                float scl) {
  int i = blockIdx.x * blockDim.x + threadIdx.x;
  if (i >= total) return;
  const int hf = i & 63;
  const int h = (i >> 6) % H;
  const int bl = i / (64 * H);
  const int l = bl & (L - 1);
  const float2 cs = tab[l * 64 + hf];
  const size_t base = ((size_t)bl * H + h) * HDIM;
  const float a = t[base + hf];
  const float b2 = t[base + hf + 64];
  f[base + hf] = __float2half((a * cs.x - b2 * cs.y) * scl);
  f[base + hf + 64] = __float2half((b2 * cs.x + a * cs.y) * scl);
}

// RoPE fp16 -> fp16 via table (pre-scaled), layout [B, L, H, 128]
__global__ void rope_h_kernel(const __half* __restrict__ t,
                              const float2* __restrict__ tab,
                              __half* __restrict__ f, int H, int total,
                              float scl) {
  int i = blockIdx.x * blockDim.x + threadIdx.x;
  if (i >= total) return;
  const int hf = i & 63;
  const int h = (i >> 6) % H;
  const int bl = i / (64 * H);
  const int l = bl & (L - 1);
  const float2 cs = tab[l * 64 + hf];
  const size_t base = ((size_t)bl * H + h) * HDIM;
  const float a = __half2float(t[base + hf]);
  const float b2 = __half2float(t[base + hf + 64]);
  f[base + hf] = __float2half((a * cs.x - b2 * cs.y) * scl);
  f[base + hf + 64] = __float2half((b2 * cs.x + a * cs.y) * scl);
}

// ======================= fp16 GEMM: 64x64 warp tiles =======================
// C[M,N] = A[M,K] @ B[N,K]^T, fp16 in, fp32 accum. 4 warps/CTA, 3-stage.
// mode 0: fp32 out; mode 1: fp16 out; mode 2: KV split.
#define BM 128
#define BN 128
#define FBK 64
#define FTILEB 16384u
#define FSTAGEB 32768u
#define GSMEM_F16 (3 * 32768)

__global__ __launch_bounds__(128, 2) void mma_gemm_f16(
    const __half* __restrict__ A, const __half* __restrict__ Bm,
    float* __restrict__ C, __half* __restrict__ C16, int M, int N, int K,
    int mode) {
  extern __shared__ char smem[];
  const uint32_t sb = smem_to_u32(smem);
  const int tid = threadIdx.x, wid = tid >> 5, lane = tid & 31;
  const int wm = wid >> 1, wn = wid & 1;
  const int m0 = blockIdx.y * BM, n0 = blockIdx.x * BN;
  const __half* pA = A + (size_t)m0 * K;
  const __half* pB = Bm + (size_t)n0 * K;

  float acc[4][8][4];
#pragma unroll
  for (int f = 0; f < 4; f++)
#pragma unroll
    for (int n = 0; n < 8; n++)
#pragma unroll
      for (int e = 0; e < 4; e++) acc[f][n][e] = 0.f;

  auto load_stage = [&](int k0, int buf) {
    const uint32_t base = sb + buf * FSTAGEB;
#pragma unroll
    for (int i = 0; i < 8; i++) {
      const int idx = i * 128 + tid;
      const int r = idx >> 3, c = idx & 7;
      const uint32_t d = base + r * 128u + ((uint32_t)(c ^ (r & 7)) << 4);
      const size_t go = (size_t)r * K + k0 + c * 8;
      cp16(d, pA + go);
      cp16(d + FTILEB, pB + go);
    }
    CP_COMMIT();
  };

  const int S = K / FBK;
  load_stage(0, 0);
  load_stage(FBK, 1);

  const int rowa = wm * 64 + (lane & 15);
  const int rowb = wn * 64 + (lane & 7) + ((lane >> 4) << 3);

  for (int s = 0; s < S; s++) {
    const int buf = s % 3;
    if (s == S - 1) CP_WAIT0(); else CP_WAIT1();
    __syncthreads();
    if (s + 2 < S) load_stage((s + 2) * FBK, (s + 2) % 3);
    const uint32_t abase = sb + buf * FSTAGEB;
    const uint32_t bbase = abase + FTILEB;
#pragma unroll
    for (int ks = 0; ks < 4; ks++) {
      uint32_t ah[4][4], bh[4][4];
      const int ca = 2 * ks + (lane >> 4);
      const int cb = 2 * ks + ((lane >> 3) & 1);
#pragma unroll
      for (int f = 0; f < 4; f++) {
        const int rr = rowa + f * 16;
        ldsm4(abase + rr * 128u + ((uint32_t)(ca ^ (rr & 7)) << 4), ah[f]);
      }
#pragma unroll
      for (int p = 0; p < 4; p++) {
        const int rr = rowb + p * 16;
        ldsm4(bbase + rr * 128u + ((uint32_t)(cb ^ (rr & 7)) << 4), bh[p]);
      }
#pragma unroll
      for (int f = 0; f < 4; f++)
#pragma unroll
        for (int n = 0; n < 8; n++)
          mma16816h(acc[f][n], ah[f], &bh[n >> 1][(n & 1) * 2]);
    }
  }

#pragma unroll
  for (int f = 0; f < 4; f++) {
    const int row = m0 + wm * 64 + f * 16 + (lane >> 2);
#pragma unroll
    for (int n = 0; n < 8; n++) {
      const int col = n0 + wn * 64 + n * 8 + (lane & 3) * 2;
      if (mode == 0) {
        *(float2*)&C[(size_t)row * N + col] =
            make_float2(acc[f][n][0], acc[f][n][1]);
        *(float2*)&C[(size_t)(row + 8) * N + col] =
            make_float2(acc[f][n][2], acc[f][n][3]);
      } else if (mode == 1) {
        *(__half2*)&C16[(size_t)row * N + col] =
            __floats2half2_rn(acc[f][n][0], acc[f][n][1]);
        *(__half2*)&C16[(size_t)(row + 8) * N + col] =
            __floats2half2_rn(acc[f][n][2], acc[f][n][3]);
      } else {
        if (col < 512) {  // K -> fp32 (RoPE input), row stride 512
          *(float2*)&C[(size_t)row * 512 + col] =
              make_float2(acc[f][n][0], acc[f][n][1]);
          *(float2*)&C[(size_t)(row + 8) * 512 + col] =
              make_float2(acc[f][n][2], acc[f][n][3]);
        } else {  // V -> fp16, row stride 512
          const int cv = col - 512;
          *(__half2*)&C16[(size_t)row * 512 + cv] =
              __floats2half2_rn(acc[f][n][0], acc[f][n][1]);
          *(__half2*)&C16[(size_t)(row + 8) * 512 + cv] =
              __floats2half2_rn(acc[f][n][2], acc[f][n][3]);
        }
      }
    }
  }
}

// ======================= fp16 flash attention =======================
// Balanced pairing; Q in smem; 2 CTAs/SM; log2-domain softmax (ex2.approx).
// Q pre-scaled by SCALE*log2e. 64-key KV stages (2-stage pipeline) processed
// as two 32-key sub-tiles.
#define AQ 128
#define NQT (L / AQ)
#define AKT 64
#define ASMEM (2 * 32768 + 32768) /* 2 KV stages (K16K+V16K each) + Q = 96KB */

__global__ __launch_bounds__(256, 2) void attn_mma(
    const __half* __restrict__ Qf, const __half* __restrict__ Kf,
    const __half* __restrict__ Vf, const int* __restrict__ mask,
    __half* __restrict__ Yf) {
  extern __shared__ char smem[];
  const uint32_t sb = smem_to_u32(smem);
  const uint32_t sbQ = sb + 2 * 32768u;
  const int pair = blockIdx.x;
  const int h = blockIdx.y, b = blockIdx.z;
  const int hkv = h >> 2;
  const int tid = threadIdx.x, w = tid >> 5, lane = tid & 31;

  const __half* khg = Kf + ((size_t)(b * L) * NKV + hkv) * 128;
  const __half* vhg = Vf + ((size_t)(b * L) * NKV + hkv) * 128;
  const int* mrow = mask + b * L;

  const int rbB = (lane & 7) + ((lane >> 4) << 3);
  const int rvB = (lane & 7) + (((lane >> 3) & 1) << 3);
  const int rowa = w * 16 + (lane & 15);
  const uint32_t qrow = sbQ + (uint32_t)rowa * 256u;

  for (int half = 0; half < 2; half++) {
    const int qt = half == 0 ? (NQT - 1 - pair) : pair;  // heavy first
    const int q0 = qt * AQ;
    __syncthreads();  // prior half fully done with smem

    // ---- stage Q into persistent smem region ----
    {
      const __half* qg = Qf + ((size_t)(b * L + q0) * NH + h) * 128;
#pragma unroll
      for (int i = 0; i < 8; i++) {
        const int idx = i * 256 + tid;
        const int r = idx >> 4, c = idx & 15;
        const uint32_t d = sbQ + r * 256u + ((uint32_t)(c ^ (r & 7)) << 4);
        cp16(d, qg + (size_t)r * (NH * 128) + c * 8);
      }
      CP_COMMIT();
      CP_WAIT0();
      __syncthreads();
    }

    float o[16][4];
#pragma unroll
    for (int nf = 0; nf < 16; nf++)
#pragma unroll
      for (int e = 0; e < 4; e++) o[nf][e] = 0.f;
    float m2[2] = {-1e30f, -1e30f}, ls[2] = {0.f, 0.f};

    auto load_kv = [&](int t, int buf) {
      const int k0 = t * AKT;
      const uint32_t base = sb + buf * 32768u;
#pragma unroll
      for (int i = 0; i < 4; i++) {
        const int idx = i * 256 + tid;
        const int r = idx >> 4, c = idx & 15;
        const uint32_t d = base + r * 256u + ((uint32_t)(c ^ (r & 7)) << 4);
        const size_t go = (size_t)(k0 + r) * (NKV * 128) + c * 8;
        cp16(d, khg + go);
        cp16(d + 16384u, vhg + go);
      }
      CP_COMMIT();
    };

    const int nkt = qt * 2 + 2;  // 64-key tiles covering [0, q0+128)
    load_kv(0, 0);

    const int qa = q0 + w * 16 + (lane >> 2);
    const int qb = qa + 8;
    const int wmax = q0 + w * 16 + 15;

    for (int kt = 0; kt < nkt; kt++) {
      const int buf = kt & 1;
      CP_WAIT0();
      __syncthreads();  // data visible + other buffer fully consumed
      if (kt + 1 < nkt) load_kv(kt + 1, (kt + 1) & 1);
      const uint32_t kb = sb + buf * 32768u;

#pragma unroll
      for (int sub = 0; sub < 2; sub++) {
        const int k0 = kt * AKT + sub * 32;
        if (k0 > wmax) continue;
        const uint32_t ksub = kb + (uint32_t)sub * 8192u;  // 32 rows * 256B

        float s[4][4];
#pragma unroll
        for (int n = 0; n < 4; n++)
#pragma unroll
          for (int e = 0; e < 4; e++) s[n][e] = 0.f;

#pragma unroll
        for (int kd = 0; kd < 8; kd++) {
          const int ca = 2 * kd + (lane >> 4);
          uint32_t qf4[4];
          ldsm4(qrow + ((uint32_t)(ca ^ (rowa & 7)) << 4), qf4);
          const int cb = 2 * kd + ((lane >> 3) & 1);
          const uint32_t b0a =
              ksub + (uint32_t)rbB * 256u + ((uint32_t)(cb ^ (rbB & 7)) << 4);
          uint32_t bh0[4], bh1[4];
          ldsm4(b0a, bh0);
          ldsm4(b0a + 16u * 256u, bh1);
#pragma unroll
          for (int n = 0; n < 4; n++) {
            const uint32_t* bp =
                (n < 2) ? &bh0[(n & 1) * 2] : &bh1[(n & 1) * 2];
            mma16816h(s[n], qf4, bp);
          }
        }

        float rmax[2] = {-1e30f, -1e30f};
#pragma unroll
        for (int n = 0; n < 4; n++) {
          const int col = k0 + n * 8 + (lane & 3) * 2;
          const bool mk0 = mrow[col] > 0, mk1 = mrow[col + 1] > 0;
          s[n][0] = (mk0 && col <= qa) ? s[n][0] : -1e30f;
          s[n][1] = (mk1 && col + 1 <= qa) ? s[n][1] : -1e30f;
          s[n][2] = (mk0 && col <= qb) ? s[n][2] : -1e30f;
          s[n][3] = (mk1 && col + 1 <= qb) ? s[n][3] : -1e30f;
          rmax[0] = fmaxf(rmax[0], fmaxf(s[n][0], s[n][1]));
          rmax[1] = fmaxf(rmax[1], fmaxf(s[n][2], s[n][3]));
        }
#pragma unroll
        for (int off = 1; off <= 2; off <<= 1) {
          rmax[0] = fmaxf(rmax[0], __shfl_xor_sync(0xffffffffu, rmax[0], off));
          rmax[1] = fmaxf(rmax[1], __shfl_xor_sync(0xffffffffu, rmax[1], off));
        }
        const float mn0 = fmaxf(m2[0], rmax[0]);
        const float mn1 = fmaxf(m2[1], rmax[1]);
        const bool noup =
            __all_sync(0xffffffffu, (mn0 == m2[0]) & (mn1 == m2[1]));
        if (!noup) {
          const float al0 = ex2(m2[0] - mn0);
          const float al1 = ex2(m2[1] - mn1);
          ls[0] *= al0;
          ls[1] *= al1;
#pragma unroll
          for (int nf = 0; nf < 16; nf++) {
            o[nf][0] *= al0;
            o[nf][1] *= al0;
            o[nf][2] *= al1;
            o[nf][3] *= al1;
          }
          m2[0] = mn0;
          m2[1] = mn1;
        }
        float ps0 = 0.f, ps1 = 0.f;
#pragma unroll
        for (int n = 0; n < 4; n++) {
          s[n][0] = ex2(s[n][0] - m2[0]);
          s[n][1] = ex2(s[n][1] - m2[0]);
          s[n][2] = ex2(s[n][2] - m2[1]);
          s[n][3] = ex2(s[n][3] - m2[1]);
          ps0 += s[n][0] + s[n][1];
          ps1 += s[n][2] + s[n][3];
        }
#pragma unroll
        for (int off = 1; off <= 2; off <<= 1) {
          ps0 += __shfl_xor_sync(0xffffffffu, ps0, off);
          ps1 += __shfl_xor_sync(0xffffffffu, ps1, off);
        }
        ls[0] += ps0;
        ls[1] += ps1;

        uint32_t pa[2][4];
#pragma unroll
        for (int ks = 0; ks < 2; ks++) {
          pa[ks][0] = pk2h(s[2 * ks][0], s[2 * ks][1]);
          pa[ks][1] = pk2h(s[2 * ks][2], s[2 * ks][3]);
          pa[ks][2] = pk2h(s[2 * ks + 1][0], s[2 * ks + 1][1]);
          pa[ks][3] = pk2h(s[2 * ks + 1][2], s[2 * ks + 1][3]);
        }

        const uint32_t vb = kb + 16384u + (uint32_t)sub * 8192u;
#pragma unroll
        for (int ks = 0; ks < 2; ks++) {
          const int rowv = 16 * ks + rvB;
#pragma unroll
          for (int j = 0; j < 8; j++) {
            const int cv = 2 * j + (lane >> 4);
            uint32_t vhf[4];
            ldsm4t(vb + (uint32_t)rowv * 256u +
                       ((uint32_t)(cv ^ (rowv & 7)) << 4),
                   vhf);
            mma16816h(o[2 * j], pa[ks], &vhf[0]);
            mma16816h(o[2 * j + 1], pa[ks], &vhf[2]);
          }
        }
      }
    }

    const float inv0 = 1.f / ls[0], inv1 = 1.f / ls[1];
    const size_t rA = (size_t)(b * L + qa) * (size_t)HID + h * 128;
    const size_t rB = rA + (size_t)8 * HID;
#pragma unroll
    for (int nf = 0; nf < 16; nf++) {
      const int d = nf * 8 + (lane & 3) * 2;
      *(__half2*)&Yf[rA + d] =
          __floats2half2_rn(o[nf][0] * inv0, o[nf][1] * inv0);
      *(__half2*)&Yf[rB + d] =
          __floats2half2_rn(o[nf][2] * inv1, o[nf][3] * inv1);
    }
  }
}

// ======================= launch =======================
extern "C" void kernel_launch(void* const* d_in, const int* in_sizes, int n_in,
                              void* d_out, int out_size) {
  const float* x = (const float*)d_in[0];
  const float* Wq = (const float*)d_in[1];
  const float* Wc = (const float*)d_in[2];
  const float* Wk = (const float*)d_in[3];
  const float* Wv = (const float*)d_in[4];
  const float* Wo = (const float*)d_in[5];
  const int* mask = (const int*)d_in[6];
  float* out = (float*)d_out;

  float* Kp;
  float2* tab;
  cudaGetSymbolAddress((void**)&Kp, g_K);
  cudaGetSymbolAddress((void**)&tab, g_tab);
  __half *xf, *cf, *qf, *kf, *vf, *yf, *wqf, *wcf, *wkvf, *wof;
  cudaGetSymbolAddress((void**)&xf, g_xf);
  cudaGetSymbolAddress((void**)&cf, g_cf);
  cudaGetSymbolAddress((void**)&qf, g_Qf);
  cudaGetSymbolAddress((void**)&kf, g_Kf);
  cudaGetSymbolAddress((void**)&vf, g_Vf);
  cudaGetSymbolAddress((void**)&yf, g_Yf);
  cudaGetSymbolAddress((void**)&wqf, g_Wqt_f);
  cudaGetSymbolAddress((void**)&wcf, g_Wct_f);
  cudaGetSymbolAddress((void**)&wkvf, g_Wkvt_f);
  cudaGetSymbolAddress((void**)&wof, g_Wot_f);

  const int M = B * L;  // 4096

  cudaFuncSetAttribute(mma_gemm_f16, cudaFuncAttributeMaxDynamicSharedMemorySize,
                       GSMEM_F16);
  cudaFuncSetAttribute(attn_mma, cudaFuncAttributeMaxDynamicSharedMemorySize,
                       ASMEM);

  // ---- main: rope table + x split; side: Wq transpose (independent) ----
  rope_tab_kernel<<<(L * 64 + 255) / 256, 256>>>(tab);                       // 0
  split_f16_kernel<<<(M * HID / 4 + 255) / 256, 256>>>(x, xf, M * HID / 4);  // 1
  tsplit_f16_kernel<<<dim3((NH * HDIM) / 32, HID / 32), 256, 0, g_ctx.side>>>(
      Wq, wqf, HID, NH * HDIM);                                              // 2

  // ---- fork: side waits for xf (+tab), Q projection (fp16 out -> yf) ----
  cudaEventRecord(g_ctx.e0, 0);
  cudaStreamWaitEvent(g_ctx.side, g_ctx.e0, 0);
  mma_gemm_f16<<<dim3((NH * HDIM) / BN, M / BM), 128, GSMEM_F16, g_ctx.side>>>(
      xf, wqf, nullptr, yf, M, NH * HDIM, HID, 1);  // 3 <- profiled slot
  const int totQ = B * L * NH * 64;
  rope_h_kernel<<<(totQ + 255) / 256, 256, 0, g_ctx.side>>>(
      yf, tab, qf, NH, totQ, SCALE_L2E);
  cudaEventRecord(g_ctx.e1, g_ctx.side);
  // Wo transpose on side stream: runs concurrently with attention
  tsplit_f16_kernel<<<dim3(HID / 32, (NH * HDIM) / 32), 256, 0, g_ctx.side>>>(
      Wo, wof, NH * HDIM, HID);
  cudaEventRecord(g_ctx.e2, g_ctx.side);

  // ---- main stream: C -> K/V chain ----
  tsplit_f16_kernel<<<dim3(LAT / 32, HID / 32), 256>>>(Wc, wcf, HID, LAT);
  tsplit_f16_kernel<<<dim3((NKV * HDIM) / 32, LAT / 32), 256>>>(
      Wk, wkvf, LAT, NKV * HDIM);  // rows 0..511
  tsplit_f16_kernel<<<dim3((NKV * HDIM) / 32, LAT / 32), 256>>>(
      Wv, wkvf + (size_t)NKV * HDIM * LAT, LAT, NKV * HDIM);  // rows 512..1023
  mma_gemm_f16<<<dim3(LAT / BN, M / BM), 128, GSMEM_F16>>>(
      xf, wcf, nullptr, cf, M, LAT, HID, 1);
  mma_gemm_f16<<<dim3((2 * NKV * HDIM) / BN, M / BM), 128, GSMEM_F16>>>(
      cf, wkvf, Kp, vf, M, 2 * NKV * HDIM, LAT, 2);
  const int totK = B * L * NKV * 64;
  rope_f16_kernel<<<(totK + 255) / 256, 256>>>(Kp, tab, kf, NKV, totK, 1.0f);

  // ---- join, attention (single balanced wave), output projection ----
  cudaStreamWaitEvent(0, g_ctx.e1, 0);
  attn_mma<<<dim3(NQT / 2, NH, B), 256, ASMEM>>>(qf, kf, vf, mask, yf);
  cudaStreamWaitEvent(0, g_ctx.e2, 0);
  mma_gemm_f16<<<dim3(HID / BN, M / BM), 128, GSMEM_F16>>>(
      yf, wof, out, nullptr, M, HID, HID, 0);
}